// round 14
// baseline (speedup 1.0000x reference)
#include <cuda_runtime.h>
#include <cuda_bf16.h>
#include <cuda_fp16.h>
#include <cstdint>

// Problem constants (fixed dataset)
#define EN    500000
#define NN    100000
#define NHH   50000
#define DD    128
#define BB    512
#define NNEG  8192
#define CAPC  24576
#define HH1   25088   // hedge split (196 tiles of 128)
#define NN1   50048   // node split (391 tiles of 128)

// ---------------- device scratch ----------------
__device__ float g_hA[(size_t)NHH * DD];   // k0 hedge out; reused: compact old, k2 compact out
__device__ float g_hB[(size_t)NHH * DD];
__device__ float g_eA[(size_t)NN * DD];    // k0 ent out; reused: old_sel for k2
__device__ float g_eB[(size_t)NN * DD];    // compact k1 ent out
__device__ float g_acc[(size_t)NN * DD];
__device__ float g_relsum[(size_t)NHH * DD];
__device__ int   g_cnt[NHH + NN];
__device__ int   g_off[NHH + NN + 1];
__device__ int   g_csr_h[EN];
__device__ int   g_csr_aux[EN];
__device__ int   g_csr_n[EN];
__device__ int   g_bsum[256];
__device__ int   g_flag[NN];
__device__ int   g_map[NN];
__device__ int   g_list[CAPC];
__device__ int   g_cntr[1];
__device__ unsigned g_Bh[65536];
__device__ unsigned g_Bl[65536];

// ---------------- helpers ----------------
__device__ __forceinline__ uint32_t smem_u32(const void* p) {
    uint32_t a;
    asm("{ .reg .u64 t; cvta.to.shared.u64 t, %1; cvt.u32.u64 %0, t; }" : "=r"(a) : "l"(p));
    return a;
}
__device__ __forceinline__ void split2h(float2 x, uint32_t& h, uint32_t& l) {
    __half2 hp = __floats2half2_rn(x.x, x.y);
    float2 hf = __half22float2(hp);
    __half2 lp = __floats2half2_rn(x.x - hf.x, x.y - hf.y);
    h = *reinterpret_cast<uint32_t*>(&hp);
    l = *reinterpret_cast<uint32_t*>(&lp);
}
__device__ __forceinline__ uint32_t cvt2h(float2 x) {
    __half2 hp = __floats2half2_rn(x.x, x.y);
    return *reinterpret_cast<uint32_t*>(&hp);
}
__device__ __forceinline__ void cp16(uint32_t s, const void* g, int sz) {
    asm volatile("cp.async.cg.shared.global [%0], [%1], 16, %2;"
                 :: "r"(s), "l"(g), "r"(sz) : "memory");
}
__device__ __forceinline__ void f4acc(float4& a, float4 b) {
    a.x += b.x; a.y += b.y; a.z += b.z; a.w += b.w;
}
#define MMA_FP16(c, a, b) \
    asm volatile("mma.sync.aligned.m16n8k16.row.col.f32.f16.f16.f32 " \
        "{%0,%1,%2,%3}, {%4,%5,%6,%7}, {%8,%9}, {%0,%1,%2,%3};" \
        : "+f"((c)[0]), "+f"((c)[1]), "+f"((c)[2]), "+f"((c)[3]) \
        : "r"((a)[0]), "r"((a)[1]), "r"((a)[2]), "r"((a)[3]), \
          "r"((b)[0]), "r"((b)[1]))

// ---------------- CSR build ----------------
__global__ void count_kernel(const int* __restrict__ node_idx,
                             const int* __restrict__ hedge_idx,
                             int* __restrict__ cnt) {
    int i = blockIdx.x * blockDim.x + threadIdx.x;
    if (i < EN) {
        atomicAdd(&cnt[hedge_idx[i]], 1);
        atomicAdd(&cnt[NHH + node_idx[i]], 1);
    }
}
__global__ void scan_pass1(const int* __restrict__ cnt, int* __restrict__ off,
                           int* __restrict__ bsum, int n) {
    __shared__ int wsum[8];
    int t = threadIdx.x, lane = t & 31, w = t >> 5;
    int b0 = blockIdx.x * 1024;
    int v[4], s = 0;
#pragma unroll
    for (int i = 0; i < 4; i++) {
        int idx = b0 + t * 4 + i;
        v[i] = (idx < n) ? cnt[idx] : 0;
        s += v[i];
    }
    int ps = s;
#pragma unroll
    for (int d = 1; d < 32; d <<= 1) {
        int x = __shfl_up_sync(0xffffffffu, ps, d);
        if (lane >= d) ps += x;
    }
    if (lane == 31) wsum[w] = ps;
    __syncthreads();
    if (t == 0) {
        int a = 0;
#pragma unroll
        for (int i = 0; i < 8; i++) { int x = wsum[i]; wsum[i] = a; a += x; }
        bsum[blockIdx.x] = a;
    }
    __syncthreads();
    int a = wsum[w] + ps - s;
#pragma unroll
    for (int i = 0; i < 4; i++) {
        int idx = b0 + t * 4 + i;
        if (idx < n) off[idx] = a;
        a += v[i];
    }
}
__global__ void scan_pass2(int* __restrict__ bsum, int nb, int* __restrict__ off, int n) {
    int lane = threadIdx.x;
    int total = 0;
    for (int base = 0; base < nb; base += 32) {
        int idx = base + lane;
        int v = (idx < nb) ? bsum[idx] : 0;
        int ps = v;
#pragma unroll
        for (int d = 1; d < 32; d <<= 1) {
            int x = __shfl_up_sync(0xffffffffu, ps, d);
            if (lane >= d) ps += x;
        }
        int chunk = __shfl_sync(0xffffffffu, ps, 31);
        if (idx < nb) bsum[idx] = total + ps - v;
        total += chunk;
    }
    if (lane == 0) off[n] = total;
}
__global__ void scan_pass3(int* __restrict__ off, const int* __restrict__ bsum, int n) {
    int i = blockIdx.x * blockDim.x + threadIdx.x;
    if (i < n) off[i] += bsum[blockIdx.x >> 2];
}
__global__ void fill_kernel(const int* __restrict__ node_idx,
                            const int* __restrict__ hedge_idx,
                            const int* __restrict__ edge_attr,
                            const int* __restrict__ v_dis,
                            const int* __restrict__ off_h, const int* __restrict__ off_n,
                            int* __restrict__ cnt,
                            int* __restrict__ csr_h, int* __restrict__ csr_aux,
                            int* __restrict__ csr_n) {
    int e = blockIdx.x * blockDim.x + threadIdx.x;
    if (e < EN) {
        int n = node_idx[e];
        int h = hedge_idx[e];
        int s = atomicSub(&cnt[h], 1) - 1;
        int p = off_h[h] + s;
        csr_h[p] = n;
        csr_aux[p] = (v_dis[n] << 16) | edge_attr[e];
        int t = atomicSub(&cnt[NHH + n], 1) - 1;
        csr_n[(off_n[n] - EN) + t] = h;
    }
}

// ---------------- mark needed nodes ----------------
__device__ __forceinline__ void mark_node(int n, int* flag, int* map, int* list, int* cntr) {
    if (atomicExch(&flag[n], 1) == 0) {
        int p = atomicAdd(cntr, 1);
        map[n] = p;
        list[p] = n;
    }
}
__global__ void mark_kernel(const int* __restrict__ pos, const int* __restrict__ neg,
                            const int* __restrict__ srcH,
                            const int* __restrict__ off, const int* __restrict__ csr_h,
                            int* __restrict__ flag, int* __restrict__ map,
                            int* __restrict__ list, int* __restrict__ cntr) {
    int t = blockIdx.x * blockDim.x + threadIdx.x;
    if (t < BB) {
        mark_node(__ldg(pos + t), flag, map, list, cntr);
    } else if (t < BB + NNEG) {
        mark_node(__ldg(neg + (t - BB)), flag, map, list, cntr);
    } else if (t < BB + NNEG + BB) {
        int h = __ldg(srcH + (t - BB - NNEG));
        int s = off[h], e = off[h + 1];
        for (int j = s; j < e; j++)
            mark_node(__ldg(csr_h + j), flag, map, list, cntr);
    }
}

// ---------------- gather aggregations (range [start,end)) ----------------
__global__ void v2e_gather_k0(const int* __restrict__ aux, const int* __restrict__ off,
                              const float* __restrict__ dis,
                              const float* __restrict__ rel,
                              float* __restrict__ relsum,
                              float* __restrict__ acc, int start, int end) {
    int h = start + ((blockIdx.x * blockDim.x + threadIdx.x) >> 5);
    int lane = threadIdx.x & 31;
    if (h >= end) return;
    int s = off[h], e = off[h + 1];
    float4 ns = make_float4(0.f, 0.f, 0.f, 0.f);
    float4 rs = make_float4(0.f, 0.f, 0.f, 0.f);
    for (int j = s; j < e; j++) {
        int av = __ldg(aux + j);
        f4acc(ns, ((const float4*)(dis + (size_t)(av >> 16) * DD))[lane]);
        f4acc(rs, ((const float4*)(rel + (size_t)(av & 0xffff) * DD))[lane]);
    }
    ((float4*)(relsum + (size_t)h * DD))[lane] = rs;
    int c = 2 * (e - s);
    float inv = 1.0f / (float)(c > 1 ? c : 1);
    float4 o;
    o.x = (ns.x + rs.x) * inv; o.y = (ns.y + rs.y) * inv;
    o.z = (ns.z + rs.z) * inv; o.w = (ns.w + rs.w) * inv;
    ((float4*)(acc + (size_t)h * DD))[lane] = o;
}
__global__ void v2e_gather(const int* __restrict__ csr, const int* __restrict__ off,
                           const float* __restrict__ ent,
                           const float* __restrict__ relsum,
                           float* __restrict__ acc, int start, int end) {
    int h = start + ((blockIdx.x * blockDim.x + threadIdx.x) >> 5);
    int lane = threadIdx.x & 31;
    if (h >= end) return;
    int s = off[h], e = off[h + 1];
    float4 s1 = ((const float4*)(relsum + (size_t)h * DD))[lane];
    float4 s2 = make_float4(0.f, 0.f, 0.f, 0.f);
    int j = s;
    for (; j + 1 < e; j += 2) {
        int i0 = __ldg(csr + j), i1 = __ldg(csr + j + 1);
        float4 a = ((const float4*)(ent + (size_t)i0 * DD))[lane];
        float4 b = ((const float4*)(ent + (size_t)i1 * DD))[lane];
        f4acc(s1, a); f4acc(s2, b);
    }
    if (j < e) {
        int i0 = __ldg(csr + j);
        f4acc(s1, ((const float4*)(ent + (size_t)i0 * DD))[lane]);
    }
    f4acc(s1, s2);
    int c = 2 * (e - s);
    float inv = 1.0f / (float)(c > 1 ? c : 1);
    s1.x *= inv; s1.y *= inv; s1.z *= inv; s1.w *= inv;
    ((float4*)(acc + (size_t)h * DD))[lane] = s1;
}
// k=2 selected hedges; ent = compact eB via map.
__global__ void v2e_gather_sel(const int* __restrict__ csr, const int* __restrict__ off,
                               const int* __restrict__ srcH,
                               const float* __restrict__ ent,
                               const int* __restrict__ map,
                               const float* __restrict__ relsum,
                               const float* __restrict__ oldfull,
                               float* __restrict__ acc_sel,
                               float* __restrict__ old_sel) {
    int b = (blockIdx.x * blockDim.x + threadIdx.x) >> 5;
    int lane = threadIdx.x & 31;
    if (b >= BB) return;
    int h = __ldg(srcH + b);
    int s = off[h], e = off[h + 1];
    float4 s1 = ((const float4*)(relsum + (size_t)h * DD))[lane];
    float4 s2 = make_float4(0.f, 0.f, 0.f, 0.f);
    int j = s;
    for (; j + 1 < e; j += 2) {
        int i0 = __ldg(map + __ldg(csr + j));
        int i1 = __ldg(map + __ldg(csr + j + 1));
        float4 a = ((const float4*)(ent + (size_t)i0 * DD))[lane];
        float4 c4 = ((const float4*)(ent + (size_t)i1 * DD))[lane];
        f4acc(s1, a); f4acc(s2, c4);
    }
    if (j < e) {
        int i0 = __ldg(map + __ldg(csr + j));
        f4acc(s1, ((const float4*)(ent + (size_t)i0 * DD))[lane]);
    }
    f4acc(s1, s2);
    int c = 2 * (e - s);
    float inv = 1.0f / (float)(c > 1 ? c : 1);
    s1.x *= inv; s1.y *= inv; s1.z *= inv; s1.w *= inv;
    ((float4*)(acc_sel + (size_t)b * DD))[lane] = s1;
    ((float4*)(old_sel + (size_t)b * DD))[lane] =
        ((const float4*)(oldfull + (size_t)h * DD))[lane];
}
__global__ void e2v_gather(const int* __restrict__ csr, const int* __restrict__ off,
                           const float* __restrict__ hemb,
                           float* __restrict__ acc, int start, int end) {
    int n = start + ((blockIdx.x * blockDim.x + threadIdx.x) >> 5);
    int lane = threadIdx.x & 31;
    if (n >= end) return;
    int s = off[n] - EN, e = off[n + 1] - EN;
    float4 s1 = make_float4(0.f, 0.f, 0.f, 0.f);
    float4 s2 = make_float4(0.f, 0.f, 0.f, 0.f);
    int j = s;
    for (; j + 1 < e; j += 2) {
        int i0 = __ldg(csr + j), i1 = __ldg(csr + j + 1);
        float4 a = ((const float4*)(hemb + (size_t)i0 * DD))[lane];
        float4 b = ((const float4*)(hemb + (size_t)i1 * DD))[lane];
        f4acc(s1, a); f4acc(s2, b);
    }
    if (j < e) {
        int i0 = __ldg(csr + j);
        f4acc(s1, ((const float4*)(hemb + (size_t)i0 * DD))[lane]);
    }
    f4acc(s1, s2);
    int c = e - s;
    float inv = 1.0f / (float)(c > 1 ? c : 1);
    s1.x *= inv; s1.y *= inv; s1.z *= inv; s1.w *= inv;
    ((float4*)(acc + (size_t)n * DD))[lane] = s1;
}
__global__ void e2v_gather_compact(const int* __restrict__ csr, const int* __restrict__ off,
                                   const float* __restrict__ hemb,
                                   const int* __restrict__ list, const int* __restrict__ cntr,
                                   const float* __restrict__ eA_full,
                                   float* __restrict__ acc,
                                   float* __restrict__ old_cmp) {
    int i = (blockIdx.x * blockDim.x + threadIdx.x) >> 5;
    int lane = threadIdx.x & 31;
    if (i >= __ldg(cntr)) return;
    int n = __ldg(list + i);
    int s = off[n] - EN, e = off[n + 1] - EN;
    float4 s1 = make_float4(0.f, 0.f, 0.f, 0.f);
    float4 s2 = make_float4(0.f, 0.f, 0.f, 0.f);
    int j = s;
    for (; j + 1 < e; j += 2) {
        int i0 = __ldg(csr + j), i1 = __ldg(csr + j + 1);
        float4 a = ((const float4*)(hemb + (size_t)i0 * DD))[lane];
        float4 b = ((const float4*)(hemb + (size_t)i1 * DD))[lane];
        f4acc(s1, a); f4acc(s2, b);
    }
    if (j < e) {
        int i0 = __ldg(csr + j);
        f4acc(s1, ((const float4*)(hemb + (size_t)i0 * DD))[lane]);
    }
    f4acc(s1, s2);
    int c = e - s;
    float inv = 1.0f / (float)(c > 1 ? c : 1);
    s1.x *= inv; s1.y *= inv; s1.z *= inv; s1.w *= inv;
    ((float4*)(acc + (size_t)i * DD))[lane] = s1;
    ((float4*)(old_cmp + (size_t)i * DD))[lane] =
        ((const float4*)(eA_full + (size_t)n * DD))[lane];
}

// ---------------- weight prep (+ zero flag/counter) ----------------
__global__ void wprep_all(const float* __restrict__ Wv_src, const float* __restrict__ Wv_self,
                          const float* __restrict__ We_src, const float* __restrict__ We_self,
                          unsigned* __restrict__ Bh, unsigned* __restrict__ Bl,
                          int* __restrict__ flag, int* __restrict__ cntr) {
    const size_t DS = (size_t)DD * DD;
    int idx = blockIdx.x * blockDim.x + threadIdx.x;
    for (int z = idx; z < NN; z += 65536) flag[z] = 0;
    if (idx == 0) cntr[0] = 0;
    if (idx >= 65536) return;
    int layer, base, Kh;
    if (idx < 8192)       { layer = 0; base = 0;     Kh = 64;  }
    else if (idx < 16384) { layer = 1; base = 8192;  Kh = 64;  }
    else if (idx < 32768) { layer = 2; base = 16384; Kh = 128; }
    else if (idx < 49152) { layer = 3; base = 32768; Kh = 128; }
    else                  { layer = 4; base = 49152; Kh = 128; }
    int li = idx - base;
    int n = li / Kh, kp = li % Kh;
    int k = kp * 2;
    const float *W1, *W2;
    switch (layer) {
        case 0: W1 = Wv_src;            W2 = nullptr;            break;
        case 1: W1 = We_src;            W2 = nullptr;            break;
        case 2: W1 = Wv_src + DS;       W2 = Wv_self + DS;       break;
        case 3: W1 = We_src + DS;       W2 = We_self + DS;       break;
        default:W1 = Wv_src + 2 * DS;   W2 = Wv_self + 2 * DS;   break;
    }
    const float* W = (k < 128) ? W1 : W2;
    int kk = k & 127;
    float2 x;
    x.x = W[(size_t)kk * 128 + n];
    x.y = W[(size_t)(kk + 1) * 128 + n];
    uint32_t h, l;
    split2h(x, h, l);
    Bh[idx] = h;
    Bl[idx] = l;
}

// ---------------- tensor-core transform (fp16 2-term) ----------------
#define AH_OFF  4096
#define BH_OFF  6656
#define BL_OFF  9216
#define STAGE   11776
#define HSTR    20
__global__ __launch_bounds__(256, 2) void transform_mma(
    const float* __restrict__ accp, const float* __restrict__ oldp,
    const unsigned* __restrict__ Bhg, const unsigned* __restrict__ Blg,
    float* __restrict__ out, int M, const int* __restrict__ Mdyn,
    int Ktot, int row_base)
{
    if (Mdyn) M = __ldg(Mdyn);
    const int row0 = row_base + blockIdx.x * 128;
    if (row0 >= M) return;
    extern __shared__ float sm[];
    uint32_t sbase = smem_u32(sm);
    const int tid = threadIdx.x;
    const int wid = tid >> 5, lane = tid & 31;
    const int wr = wid & 3, wc = wid >> 2;
    const int qr = lane >> 2, qc = lane & 3;
    const int Kh = Ktot >> 1;

    float C[2][8][4];
#pragma unroll
    for (int mf = 0; mf < 2; mf++)
#pragma unroll
        for (int nf = 0; nf < 8; nf++)
#pragma unroll
            for (int j = 0; j < 4; j++) C[mf][nf][j] = 0.0f;

    const int nch = Ktot >> 5;

#define PREFETCH(CH) do { \
    int _b = (CH) & 1; \
    uint32_t _aS = sbase + (uint32_t)(_b * STAGE * 4); \
    uint32_t _bhS = _aS + BH_OFF * 4; \
    uint32_t _blS = _aS + BL_OFF * 4; \
    int _kk = (CH) << 5; \
    const float* _sp = (_kk >= 128) ? oldp : accp; \
    int _sc = (_kk >= 128) ? (_kk - 128) : _kk; \
    _Pragma("unroll") \
    for (int _i = 0; _i < 4; _i++) { \
        int _idx = tid + _i * 256; \
        int _r = _idx >> 3, _c4 = _idx & 7; \
        int _gr = row0 + _r; \
        int _sz = (_gr < M) ? 16 : 0; \
        const float* _g = _sp + (size_t)min(_gr, M - 1) * 128 + _sc + _c4 * 4; \
        cp16(_aS + (uint32_t)((_r * 32 + _c4 * 4) * 4), _g, _sz); \
    } \
    _Pragma("unroll") \
    for (int _i = 0; _i < 2; _i++) { \
        int _idx = tid + _i * 256; \
        int _n = _idx >> 2, _c4 = _idx & 3; \
        cp16(_bhS + (uint32_t)((_n * HSTR + _c4 * 4) * 4), \
             Bhg + (size_t)_n * Kh + (_kk >> 1) + _c4 * 4, 16); \
        cp16(_blS + (uint32_t)((_n * HSTR + _c4 * 4) * 4), \
             Blg + (size_t)_n * Kh + (_kk >> 1) + _c4 * 4, 16); \
    } \
} while (0)

    PREFETCH(0);
    asm volatile("cp.async.commit_group;" ::: "memory");

    for (int ch = 0; ch < nch; ch++) {
        if (ch + 1 < nch) {
            PREFETCH(ch + 1);
            asm volatile("cp.async.commit_group;" ::: "memory");
            asm volatile("cp.async.wait_group 1;" ::: "memory");
        } else {
            asm volatile("cp.async.wait_group 0;" ::: "memory");
        }
        __syncthreads();

        int b = ch & 1;
        const float* As = sm + b * STAGE;
        unsigned* AHs = (unsigned*)(sm + b * STAGE + AH_OFF);
        const unsigned* BhS = (const unsigned*)(sm + b * STAGE + BH_OFF);
        const unsigned* BlS = (const unsigned*)(sm + b * STAGE + BL_OFF);

#pragma unroll
        for (int i = 0; i < 8; i++) {
            int idx = tid + i * 256;
            int r = idx >> 4, p = idx & 15;
            float2 x = *(const float2*)(As + r * 32 + 2 * p);
            AHs[r * HSTR + p] = cvt2h(x);
        }
        __syncthreads();

#pragma unroll
        for (int ks = 0; ks < 2; ks++) {
            int kb = ks * 8 + qc;
            uint32_t ah[2][4];
#pragma unroll
            for (int mf = 0; mf < 2; mf++) {
                int r0 = wr * 32 + mf * 16 + qr;
                ah[mf][0] = AHs[r0 * HSTR + kb];
                ah[mf][1] = AHs[(r0 + 8) * HSTR + kb];
                ah[mf][2] = AHs[r0 * HSTR + kb + 4];
                ah[mf][3] = AHs[(r0 + 8) * HSTR + kb + 4];
            }
            uint32_t bh[8][2], bl[8][2];
#pragma unroll
            for (int nf = 0; nf < 8; nf++) {
                int n = wc * 64 + nf * 8 + qr;
                bh[nf][0] = BhS[n * HSTR + kb];
                bh[nf][1] = BhS[n * HSTR + kb + 4];
                bl[nf][0] = BlS[n * HSTR + kb];
                bl[nf][1] = BlS[n * HSTR + kb + 4];
            }
#pragma unroll
            for (int mf = 0; mf < 2; mf++)
#pragma unroll
                for (int nf = 0; nf < 8; nf++) {
                    MMA_FP16(C[mf][nf], ah[mf], bh[nf]);
                    MMA_FP16(C[mf][nf], ah[mf], bl[nf]);
                }
        }
        __syncthreads();
    }

#pragma unroll
    for (int mf = 0; mf < 2; mf++) {
        int rA = row0 + wr * 32 + mf * 16 + qr;
#pragma unroll
        for (int nf = 0; nf < 8; nf++) {
            int c = wc * 64 + nf * 8 + qc * 2;
            if (rA < M) {
                float2 v;
                v.x = fmaxf(C[mf][nf][0], 0.f);
                v.y = fmaxf(C[mf][nf][1], 0.f);
                *(float2*)(out + (size_t)rA * 128 + c) = v;
            }
            if (rA + 8 < M) {
                float2 v;
                v.x = fmaxf(C[mf][nf][2], 0.f);
                v.y = fmaxf(C[mf][nf][3], 0.f);
                *(float2*)(out + (size_t)(rA + 8) * 128 + c) = v;
            }
        }
    }
}

// ---------------- final gather ----------------
__global__ void gather_out(const float* __restrict__ hSel,
                           const float* __restrict__ eB,
                           const int* __restrict__ map,
                           const int* __restrict__ pos,
                           const int* __restrict__ neg,
                           float* __restrict__ out) {
    int gw = (blockIdx.x * blockDim.x + threadIdx.x) >> 5;
    int lane = threadIdx.x & 31;
    const int TOT = BB + BB + NNEG;
    if (gw >= TOT) return;
    const float* src;
    if (gw < BB)          src = hSel + (size_t)gw * DD;
    else if (gw < 2 * BB) src = eB + (size_t)__ldg(map + pos[gw - BB]) * DD;
    else                  src = eB + (size_t)__ldg(map + neg[gw - 2 * BB]) * DD;
    ((float4*)out)[(size_t)gw * 32 + lane] = ((const float4*)src)[lane];
}

// ---------------- launch ----------------
extern "C" void kernel_launch(void* const* d_in, const int* in_sizes, int n_in,
                              void* d_out, int out_size) {
    const int* node_idx  = (const int*)d_in[0];
    const int* hedge_idx = (const int*)d_in[1];
    const int* edge_attr = (const int*)d_in[2];
    const int* v_dis     = (const int*)d_in[3];
    const int* src_h     = (const int*)d_in[4];
    const int* pos_ids   = (const int*)d_in[5];
    const int* neg_ids   = (const int*)d_in[6];
    const float* dis_emb = (const float*)d_in[7];
    const float* rel_emb = (const float*)d_in[8];
    const float* Wv_src  = (const float*)d_in[9];
    const float* Wv_self = (const float*)d_in[10];
    const float* We_src  = (const float*)d_in[11];
    const float* We_self = (const float*)d_in[12];
    float* out = (float*)d_out;

    float *hA, *hB, *eA, *eB, *acc, *relsum;
    int *cnt, *off, *csrh, *csraux, *csrn, *bsum, *flag, *map, *list, *cntr;
    unsigned *Bh, *Bl;
    cudaGetSymbolAddress((void**)&hA,     g_hA);
    cudaGetSymbolAddress((void**)&hB,     g_hB);
    cudaGetSymbolAddress((void**)&eA,     g_eA);
    cudaGetSymbolAddress((void**)&eB,     g_eB);
    cudaGetSymbolAddress((void**)&acc,    g_acc);
    cudaGetSymbolAddress((void**)&relsum, g_relsum);
    cudaGetSymbolAddress((void**)&cnt,    g_cnt);
    cudaGetSymbolAddress((void**)&off,    g_off);
    cudaGetSymbolAddress((void**)&csrh,   g_csr_h);
    cudaGetSymbolAddress((void**)&csraux, g_csr_aux);
    cudaGetSymbolAddress((void**)&csrn,   g_csr_n);
    cudaGetSymbolAddress((void**)&bsum,   g_bsum);
    cudaGetSymbolAddress((void**)&flag,   g_flag);
    cudaGetSymbolAddress((void**)&map,    g_map);
    cudaGetSymbolAddress((void**)&list,   g_list);
    cudaGetSymbolAddress((void**)&cntr,   g_cntr);
    cudaGetSymbolAddress((void**)&Bh,     g_Bh);
    cudaGetSymbolAddress((void**)&Bl,     g_Bl);

    // one-time stream/event setup (host objects only; no device allocations)
    static cudaStream_t s1 = nullptr;
    static cudaEvent_t evFork, evW, evFill, evM, evG1, evG2, evG3, evL1, evL2, evL3;
    if (!s1) {
        cudaStreamCreateWithFlags(&s1, cudaStreamNonBlocking);
        cudaEventCreateWithFlags(&evFork, cudaEventDisableTiming);
        cudaEventCreateWithFlags(&evW,    cudaEventDisableTiming);
        cudaEventCreateWithFlags(&evFill, cudaEventDisableTiming);
        cudaEventCreateWithFlags(&evM,    cudaEventDisableTiming);
        cudaEventCreateWithFlags(&evG1,   cudaEventDisableTiming);
        cudaEventCreateWithFlags(&evG2,   cudaEventDisableTiming);
        cudaEventCreateWithFlags(&evG3,   cudaEventDisableTiming);
        cudaEventCreateWithFlags(&evL1,   cudaEventDisableTiming);
        cudaEventCreateWithFlags(&evL2,   cudaEventDisableTiming);
        cudaEventCreateWithFlags(&evL3,   cudaEventDisableTiming);
    }

    const int SMEM_TC = STAGE * 2 * 4;
    cudaFuncSetAttribute(transform_mma, cudaFuncAttributeMaxDynamicSharedMemorySize, SMEM_TC);

    const int SELW = (BB * 32 + 255) / 256;
    const int SELB = (BB + 127) / 128;
    const int CMPW = (CAPC * 32 + 255) / 256;
    const int CMPB = (CAPC + 127) / 128;
    const int MARKB = (BB + NNEG + BB + 255) / 256;
    const int OW  = ((BB + BB + NNEG) * 32 + 255) / 256;
    const int o0 = 0, o1 = 8192, o2 = 16384, o3 = 32768, o4 = 49152;
    // half-range gather grids
    const int GH0 = (HH1 * 32 + 255) / 256;                 // hedge first half
    const int GH1 = ((NHH - HH1) * 32 + 255) / 256;         // hedge second half
    const int GN0 = (NN1 * 32 + 255) / 256;                 // node first half
    const int GN1 = ((NN - NN1) * 32 + 255) / 256;          // node second half
    const int TH0 = HH1 / 128, TH1 = (NHH - HH1 + 127) / 128;
    const int TN0 = NN1 / 128, TN1 = (NN - NN1 + 127) / 128;

    // ---- fork s1 from capture stream ----
    cudaEventRecord(evFork, 0);
    cudaStreamWaitEvent(s1, evFork, 0);

    // s1: weight prep (zeros flag/cntr too)
    wprep_all<<<256, 256, 0, s1>>>(Wv_src, Wv_self, We_src, We_self, Bh, Bl, flag, cntr);
    cudaEventRecord(evW, s1);

    // s0: CSR build
    cudaMemsetAsync(cnt, 0, (NHH + NN) * sizeof(int));
    count_kernel<<<(EN + 255) / 256, 256>>>(node_idx, hedge_idx, cnt);
    {
        const int NTOT = NHH + NN;
        int nb = (NTOT + 1023) / 1024;
        scan_pass1<<<nb, 256>>>(cnt, off, bsum, NTOT);
        scan_pass2<<<1, 32>>>(bsum, nb, off, NTOT);
        scan_pass3<<<(NTOT + 255) / 256, 256>>>(off, bsum, NTOT);
    }
    fill_kernel<<<(EN + 255) / 256, 256>>>(node_idx, hedge_idx, edge_attr, v_dis,
                                           off, off + NHH, cnt, csrh, csraux, csrn);
    cudaEventRecord(evFill, 0);

    // s1: mark (needs fill + wprep's flag zeroing; s1 order gives the latter)
    cudaStreamWaitEvent(s1, evFill, 0);
    mark_kernel<<<MARKB, 256, 0, s1>>>(pos_ids, neg_ids, src_h, off, csrh,
                                       flag, map, list, cntr);
    cudaEventRecord(evM, s1);

    // ---- L1: k=0 hedge (skewed halves) ----
    v2e_gather_k0<<<GH0, 256>>>(csraux, off, dis_emb, rel_emb, relsum, acc, 0, HH1);
    cudaEventRecord(evG1, 0);
    cudaStreamWaitEvent(0, evW, 0);
    transform_mma<<<TH0, 256, SMEM_TC>>>(acc, nullptr, Bh + o0, Bl + o0, hA, NHH, nullptr, 128, 0);
    cudaStreamWaitEvent(s1, evG1, 0);
    v2e_gather_k0<<<GH1, 256, 0, s1>>>(csraux, off, dis_emb, rel_emb, relsum, acc, HH1, NHH);
    transform_mma<<<TH1, 256, SMEM_TC, s1>>>(acc, nullptr, Bh + o0, Bl + o0, hA, NHH, nullptr, 128, HH1);
    cudaEventRecord(evL1, s1);
    cudaStreamWaitEvent(0, evL1, 0);

    // ---- L2: k=0 ent (skewed halves; reads full hA) ----
    e2v_gather<<<GN0, 256>>>(csrn, off + NHH, hA, acc, 0, NN1);
    cudaEventRecord(evG2, 0);
    transform_mma<<<TN0, 256, SMEM_TC>>>(acc, nullptr, Bh + o1, Bl + o1, eA, NN, nullptr, 128, 0);
    cudaStreamWaitEvent(s1, evG2, 0);
    e2v_gather<<<GN1, 256, 0, s1>>>(csrn, off + NHH, hA, acc, NN1, NN);
    transform_mma<<<TN1, 256, SMEM_TC, s1>>>(acc, nullptr, Bh + o1, Bl + o1, eA, NN, nullptr, 128, NN1);
    cudaEventRecord(evL2, s1);
    cudaStreamWaitEvent(0, evL2, 0);

    // ---- L3: k=1 hedge (skewed halves; reads full eA, old hA) ----
    v2e_gather<<<GH0, 256>>>(csrh, off, eA, relsum, acc, 0, HH1);
    cudaEventRecord(evG3, 0);
    transform_mma<<<TH0, 256, SMEM_TC>>>(acc, hA, Bh + o2, Bl + o2, hB, NHH, nullptr, 256, 0);
    cudaStreamWaitEvent(s1, evG3, 0);
    v2e_gather<<<GH1, 256, 0, s1>>>(csrh, off, eA, relsum, acc, HH1, NHH);
    transform_mma<<<TH1, 256, SMEM_TC, s1>>>(acc, hA, Bh + o2, Bl + o2, hB, NHH, nullptr, 256, HH1);
    cudaEventRecord(evL3, s1);
    cudaStreamWaitEvent(0, evL3, 0);
    cudaStreamWaitEvent(0, evM, 0);

    // ---- k=1 ent: compact rows only ----
    e2v_gather_compact<<<CMPW, 256>>>(csrn, off + NHH, hB, list, cntr, eA, acc, hA);
    transform_mma<<<CMPB, 256, SMEM_TC>>>(acc, hA, Bh + o3, Bl + o3, eB, CAPC, cntr, 256, 0);

    // ---- k=2: only the 512 source hedges ----
    v2e_gather_sel<<<SELW, 256>>>(csrh, off, src_h, eB, map, relsum, hB, acc, eA);
    transform_mma<<<SELB, 256, SMEM_TC>>>(acc, eA, Bh + o4, Bl + o4, hA, BB, nullptr, 256, 0);

    // ---- outputs ----
    gather_out<<<OW, 256>>>(hA, eB, map, pos_ids, neg_ids, out);
}

// round 15
// speedup vs baseline: 1.0959x; 1.0959x over previous
#include <cuda_runtime.h>
#include <cuda_bf16.h>
#include <cuda_fp16.h>
#include <cstdint>

// Problem constants (fixed dataset)
#define EN    500000
#define NN    100000
#define NHH   50000
#define DD    128
#define BB    512
#define NNEG  8192
#define CAPC  24576

// ---------------- device scratch ----------------
__device__ float g_hA[(size_t)NHH * DD];   // k0 hedge out; reused: compact old, k2 compact out
__device__ float g_hB[(size_t)NHH * DD];
__device__ float g_eA[(size_t)NN * DD];    // k0 ent out; reused: old_sel for k2
__device__ float g_eB[(size_t)NN * DD];    // compact k1 ent out
__device__ float g_acc[(size_t)NN * DD];
__device__ float g_relsum[(size_t)NHH * DD];
__device__ int   g_cnt[NHH + NN];
__device__ int   g_off[NHH + NN + 1];
__device__ int   g_csr_h[EN];
__device__ int   g_csr_aux[EN];
__device__ int   g_csr_n[EN];
__device__ int   g_bsum[256];
__device__ int   g_flag[NN];
__device__ int   g_map[NN];
__device__ int   g_list[CAPC];
__device__ int   g_cntr[1];
__device__ unsigned g_Bh[65536];
__device__ unsigned g_Bl[65536];

// ---------------- helpers ----------------
__device__ __forceinline__ uint32_t smem_u32(const void* p) {
    uint32_t a;
    asm("{ .reg .u64 t; cvta.to.shared.u64 t, %1; cvt.u32.u64 %0, t; }" : "=r"(a) : "l"(p));
    return a;
}
__device__ __forceinline__ void split2h(float2 x, uint32_t& h, uint32_t& l) {
    __half2 hp = __floats2half2_rn(x.x, x.y);
    float2 hf = __half22float2(hp);
    __half2 lp = __floats2half2_rn(x.x - hf.x, x.y - hf.y);
    h = *reinterpret_cast<uint32_t*>(&hp);
    l = *reinterpret_cast<uint32_t*>(&lp);
}
__device__ __forceinline__ uint32_t cvt2h(float2 x) {
    __half2 hp = __floats2half2_rn(x.x, x.y);
    return *reinterpret_cast<uint32_t*>(&hp);
}
__device__ __forceinline__ void cp16(uint32_t s, const void* g, int sz) {
    asm volatile("cp.async.cg.shared.global [%0], [%1], 16, %2;"
                 :: "r"(s), "l"(g), "r"(sz) : "memory");
}
__device__ __forceinline__ void f4acc(float4& a, float4 b) {
    a.x += b.x; a.y += b.y; a.z += b.z; a.w += b.w;
}
#define MMA_FP16(c, a, b) \
    asm volatile("mma.sync.aligned.m16n8k16.row.col.f32.f16.f16.f32 " \
        "{%0,%1,%2,%3}, {%4,%5,%6,%7}, {%8,%9}, {%0,%1,%2,%3};" \
        : "+f"((c)[0]), "+f"((c)[1]), "+f"((c)[2]), "+f"((c)[3]) \
        : "r"((a)[0]), "r"((a)[1]), "r"((a)[2]), "r"((a)[3]), \
          "r"((b)[0]), "r"((b)[1]))

// ---------------- CSR build ----------------
__global__ void count_kernel(const int* __restrict__ node_idx,
                             const int* __restrict__ hedge_idx,
                             int* __restrict__ cnt) {
    int i = blockIdx.x * blockDim.x + threadIdx.x;
    if (i < EN) {
        atomicAdd(&cnt[hedge_idx[i]], 1);
        atomicAdd(&cnt[NHH + node_idx[i]], 1);
    }
}
__global__ void scan_pass1(const int* __restrict__ cnt, int* __restrict__ off,
                           int* __restrict__ bsum, int n) {
    __shared__ int wsum[8];
    int t = threadIdx.x, lane = t & 31, w = t >> 5;
    int b0 = blockIdx.x * 1024;
    int v[4], s = 0;
#pragma unroll
    for (int i = 0; i < 4; i++) {
        int idx = b0 + t * 4 + i;
        v[i] = (idx < n) ? cnt[idx] : 0;
        s += v[i];
    }
    int ps = s;
#pragma unroll
    for (int d = 1; d < 32; d <<= 1) {
        int x = __shfl_up_sync(0xffffffffu, ps, d);
        if (lane >= d) ps += x;
    }
    if (lane == 31) wsum[w] = ps;
    __syncthreads();
    if (t == 0) {
        int a = 0;
#pragma unroll
        for (int i = 0; i < 8; i++) { int x = wsum[i]; wsum[i] = a; a += x; }
        bsum[blockIdx.x] = a;
    }
    __syncthreads();
    int a = wsum[w] + ps - s;
#pragma unroll
    for (int i = 0; i < 4; i++) {
        int idx = b0 + t * 4 + i;
        if (idx < n) off[idx] = a;
        a += v[i];
    }
}
__global__ void scan_pass2(int* __restrict__ bsum, int nb, int* __restrict__ off, int n) {
    int lane = threadIdx.x;
    int total = 0;
    for (int base = 0; base < nb; base += 32) {
        int idx = base + lane;
        int v = (idx < nb) ? bsum[idx] : 0;
        int ps = v;
#pragma unroll
        for (int d = 1; d < 32; d <<= 1) {
            int x = __shfl_up_sync(0xffffffffu, ps, d);
            if (lane >= d) ps += x;
        }
        int chunk = __shfl_sync(0xffffffffu, ps, 31);
        if (idx < nb) bsum[idx] = total + ps - v;
        total += chunk;
    }
    if (lane == 0) off[n] = total;
}
__global__ void scan_pass3(int* __restrict__ off, const int* __restrict__ bsum, int n) {
    int i = blockIdx.x * blockDim.x + threadIdx.x;
    if (i < n) off[i] += bsum[blockIdx.x >> 2];
}
__global__ void fill_kernel(const int* __restrict__ node_idx,
                            const int* __restrict__ hedge_idx,
                            const int* __restrict__ edge_attr,
                            const int* __restrict__ v_dis,
                            const int* __restrict__ off_h, const int* __restrict__ off_n,
                            int* __restrict__ cnt,
                            int* __restrict__ csr_h, int* __restrict__ csr_aux,
                            int* __restrict__ csr_n) {
    int e = blockIdx.x * blockDim.x + threadIdx.x;
    if (e < EN) {
        int n = node_idx[e];
        int h = hedge_idx[e];
        int s = atomicSub(&cnt[h], 1) - 1;
        int p = off_h[h] + s;
        csr_h[p] = n;
        csr_aux[p] = (v_dis[n] << 16) | edge_attr[e];
        int t = atomicSub(&cnt[NHH + n], 1) - 1;
        csr_n[(off_n[n] - EN) + t] = h;
    }
}

// ---------------- mark needed nodes ----------------
__device__ __forceinline__ void mark_node(int n, int* flag, int* map, int* list, int* cntr) {
    if (atomicExch(&flag[n], 1) == 0) {
        int p = atomicAdd(cntr, 1);
        map[n] = p;
        list[p] = n;
    }
}
__global__ void mark_kernel(const int* __restrict__ pos, const int* __restrict__ neg,
                            const int* __restrict__ srcH,
                            const int* __restrict__ off, const int* __restrict__ csr_h,
                            int* __restrict__ flag, int* __restrict__ map,
                            int* __restrict__ list, int* __restrict__ cntr) {
    int t = blockIdx.x * blockDim.x + threadIdx.x;
    if (t < BB) {
        mark_node(__ldg(pos + t), flag, map, list, cntr);
    } else if (t < BB + NNEG) {
        mark_node(__ldg(neg + (t - BB)), flag, map, list, cntr);
    } else if (t < BB + NNEG + BB) {
        int h = __ldg(srcH + (t - BB - NNEG));
        int s = off[h], e = off[h + 1];
        for (int j = s; j < e; j++)
            mark_node(__ldg(csr_h + j), flag, map, list, cntr);
    }
}

// ---------------- gather aggregations (fp32, 2-way) ----------------
__global__ void v2e_gather_k0(const int* __restrict__ aux, const int* __restrict__ off,
                              const float* __restrict__ dis,
                              const float* __restrict__ rel,
                              float* __restrict__ relsum,
                              float* __restrict__ acc) {
    int h = (blockIdx.x * blockDim.x + threadIdx.x) >> 5;
    int lane = threadIdx.x & 31;
    if (h >= NHH) return;
    int s = off[h], e = off[h + 1];
    float4 ns = make_float4(0.f, 0.f, 0.f, 0.f);
    float4 rs = make_float4(0.f, 0.f, 0.f, 0.f);
    for (int j = s; j < e; j++) {
        int av = __ldg(aux + j);
        f4acc(ns, ((const float4*)(dis + (size_t)(av >> 16) * DD))[lane]);
        f4acc(rs, ((const float4*)(rel + (size_t)(av & 0xffff) * DD))[lane]);
    }
    ((float4*)(relsum + (size_t)h * DD))[lane] = rs;
    int c = 2 * (e - s);
    float inv = 1.0f / (float)(c > 1 ? c : 1);
    float4 o;
    o.x = (ns.x + rs.x) * inv; o.y = (ns.y + rs.y) * inv;
    o.z = (ns.z + rs.z) * inv; o.w = (ns.w + rs.w) * inv;
    ((float4*)(acc + (size_t)h * DD))[lane] = o;
}
__global__ void v2e_gather(const int* __restrict__ csr, const int* __restrict__ off,
                           const float* __restrict__ ent,
                           const float* __restrict__ relsum,
                           float* __restrict__ acc) {
    int h = (blockIdx.x * blockDim.x + threadIdx.x) >> 5;
    int lane = threadIdx.x & 31;
    if (h >= NHH) return;
    int s = off[h], e = off[h + 1];
    float4 s1 = ((const float4*)(relsum + (size_t)h * DD))[lane];
    float4 s2 = make_float4(0.f, 0.f, 0.f, 0.f);
    int j = s;
    for (; j + 1 < e; j += 2) {
        int i0 = __ldg(csr + j), i1 = __ldg(csr + j + 1);
        float4 a = ((const float4*)(ent + (size_t)i0 * DD))[lane];
        float4 b = ((const float4*)(ent + (size_t)i1 * DD))[lane];
        f4acc(s1, a); f4acc(s2, b);
    }
    if (j < e) {
        int i0 = __ldg(csr + j);
        f4acc(s1, ((const float4*)(ent + (size_t)i0 * DD))[lane]);
    }
    f4acc(s1, s2);
    int c = 2 * (e - s);
    float inv = 1.0f / (float)(c > 1 ? c : 1);
    s1.x *= inv; s1.y *= inv; s1.z *= inv; s1.w *= inv;
    ((float4*)(acc + (size_t)h * DD))[lane] = s1;
}
// k=2 selected hedges; ent = compact eB via map.
__global__ void v2e_gather_sel(const int* __restrict__ csr, const int* __restrict__ off,
                               const int* __restrict__ srcH,
                               const float* __restrict__ ent,
                               const int* __restrict__ map,
                               const float* __restrict__ relsum,
                               const float* __restrict__ oldfull,
                               float* __restrict__ acc_sel,
                               float* __restrict__ old_sel) {
    int b = (blockIdx.x * blockDim.x + threadIdx.x) >> 5;
    int lane = threadIdx.x & 31;
    if (b >= BB) return;
    int h = __ldg(srcH + b);
    int s = off[h], e = off[h + 1];
    float4 s1 = ((const float4*)(relsum + (size_t)h * DD))[lane];
    float4 s2 = make_float4(0.f, 0.f, 0.f, 0.f);
    int j = s;
    for (; j + 1 < e; j += 2) {
        int i0 = __ldg(map + __ldg(csr + j));
        int i1 = __ldg(map + __ldg(csr + j + 1));
        float4 a = ((const float4*)(ent + (size_t)i0 * DD))[lane];
        float4 c4 = ((const float4*)(ent + (size_t)i1 * DD))[lane];
        f4acc(s1, a); f4acc(s2, c4);
    }
    if (j < e) {
        int i0 = __ldg(map + __ldg(csr + j));
        f4acc(s1, ((const float4*)(ent + (size_t)i0 * DD))[lane]);
    }
    f4acc(s1, s2);
    int c = 2 * (e - s);
    float inv = 1.0f / (float)(c > 1 ? c : 1);
    s1.x *= inv; s1.y *= inv; s1.z *= inv; s1.w *= inv;
    ((float4*)(acc_sel + (size_t)b * DD))[lane] = s1;
    ((float4*)(old_sel + (size_t)b * DD))[lane] =
        ((const float4*)(oldfull + (size_t)h * DD))[lane];
}
__global__ void e2v_gather(const int* __restrict__ csr, const int* __restrict__ off,
                           const float* __restrict__ hemb,
                           float* __restrict__ acc) {
    int n = (blockIdx.x * blockDim.x + threadIdx.x) >> 5;
    int lane = threadIdx.x & 31;
    if (n >= NN) return;
    int s = off[n] - EN, e = off[n + 1] - EN;
    float4 s1 = make_float4(0.f, 0.f, 0.f, 0.f);
    float4 s2 = make_float4(0.f, 0.f, 0.f, 0.f);
    int j = s;
    for (; j + 1 < e; j += 2) {
        int i0 = __ldg(csr + j), i1 = __ldg(csr + j + 1);
        float4 a = ((const float4*)(hemb + (size_t)i0 * DD))[lane];
        float4 b = ((const float4*)(hemb + (size_t)i1 * DD))[lane];
        f4acc(s1, a); f4acc(s2, b);
    }
    if (j < e) {
        int i0 = __ldg(csr + j);
        f4acc(s1, ((const float4*)(hemb + (size_t)i0 * DD))[lane]);
    }
    f4acc(s1, s2);
    int c = e - s;
    float inv = 1.0f / (float)(c > 1 ? c : 1);
    s1.x *= inv; s1.y *= inv; s1.z *= inv; s1.w *= inv;
    ((float4*)(acc + (size_t)n * DD))[lane] = s1;
}
__global__ void e2v_gather_compact(const int* __restrict__ csr, const int* __restrict__ off,
                                   const float* __restrict__ hemb,
                                   const int* __restrict__ list, const int* __restrict__ cntr,
                                   const float* __restrict__ eA_full,
                                   float* __restrict__ acc,
                                   float* __restrict__ old_cmp) {
    int i = (blockIdx.x * blockDim.x + threadIdx.x) >> 5;
    int lane = threadIdx.x & 31;
    if (i >= __ldg(cntr)) return;
    int n = __ldg(list + i);
    int s = off[n] - EN, e = off[n + 1] - EN;
    float4 s1 = make_float4(0.f, 0.f, 0.f, 0.f);
    float4 s2 = make_float4(0.f, 0.f, 0.f, 0.f);
    int j = s;
    for (; j + 1 < e; j += 2) {
        int i0 = __ldg(csr + j), i1 = __ldg(csr + j + 1);
        float4 a = ((const float4*)(hemb + (size_t)i0 * DD))[lane];
        float4 b = ((const float4*)(hemb + (size_t)i1 * DD))[lane];
        f4acc(s1, a); f4acc(s2, b);
    }
    if (j < e) {
        int i0 = __ldg(csr + j);
        f4acc(s1, ((const float4*)(hemb + (size_t)i0 * DD))[lane]);
    }
    f4acc(s1, s2);
    int c = e - s;
    float inv = 1.0f / (float)(c > 1 ? c : 1);
    s1.x *= inv; s1.y *= inv; s1.z *= inv; s1.w *= inv;
    ((float4*)(acc + (size_t)i * DD))[lane] = s1;
    ((float4*)(old_cmp + (size_t)i * DD))[lane] =
        ((const float4*)(eA_full + (size_t)n * DD))[lane];
}

// ---------------- weight prep (+ zero flag/counter) ----------------
__global__ void wprep_all(const float* __restrict__ Wv_src, const float* __restrict__ Wv_self,
                          const float* __restrict__ We_src, const float* __restrict__ We_self,
                          unsigned* __restrict__ Bh, unsigned* __restrict__ Bl,
                          int* __restrict__ flag, int* __restrict__ cntr) {
    const size_t DS = (size_t)DD * DD;
    int idx = blockIdx.x * blockDim.x + threadIdx.x;
    for (int z = idx; z < NN; z += 65536) flag[z] = 0;
    if (idx == 0) cntr[0] = 0;
    if (idx >= 65536) return;
    int layer, base, Kh;
    if (idx < 8192)       { layer = 0; base = 0;     Kh = 64;  }
    else if (idx < 16384) { layer = 1; base = 8192;  Kh = 64;  }
    else if (idx < 32768) { layer = 2; base = 16384; Kh = 128; }
    else if (idx < 49152) { layer = 3; base = 32768; Kh = 128; }
    else                  { layer = 4; base = 49152; Kh = 128; }
    int li = idx - base;
    int n = li / Kh, kp = li % Kh;
    int k = kp * 2;
    const float *W1, *W2;
    switch (layer) {
        case 0: W1 = Wv_src;            W2 = nullptr;            break;
        case 1: W1 = We_src;            W2 = nullptr;            break;
        case 2: W1 = Wv_src + DS;       W2 = Wv_self + DS;       break;
        case 3: W1 = We_src + DS;       W2 = We_self + DS;       break;
        default:W1 = Wv_src + 2 * DS;   W2 = Wv_self + 2 * DS;   break;
    }
    const float* W = (k < 128) ? W1 : W2;
    int kk = k & 127;
    float2 x;
    x.x = W[(size_t)kk * 128 + n];
    x.y = W[(size_t)(kk + 1) * 128 + n];
    uint32_t h, l;
    split2h(x, h, l);
    Bh[idx] = h;
    Bl[idx] = l;
}

// ---------------- tensor-core transform (fp16 2-term) ----------------
#define AH_OFF  4096
#define BH_OFF  6656
#define BL_OFF  9216
#define STAGE   11776
#define HSTR    20
__global__ __launch_bounds__(256, 2) void transform_mma(
    const float* __restrict__ accp, const float* __restrict__ oldp,
    const unsigned* __restrict__ Bhg, const unsigned* __restrict__ Blg,
    float* __restrict__ out, int M, const int* __restrict__ Mdyn, int Ktot)
{
    if (Mdyn) M = __ldg(Mdyn);
    const int row0 = blockIdx.x * 128;
    if (row0 >= M) return;
    extern __shared__ float sm[];
    uint32_t sbase = smem_u32(sm);
    const int tid = threadIdx.x;
    const int wid = tid >> 5, lane = tid & 31;
    const int wr = wid & 3, wc = wid >> 2;
    const int qr = lane >> 2, qc = lane & 3;
    const int Kh = Ktot >> 1;

    float C[2][8][4];
#pragma unroll
    for (int mf = 0; mf < 2; mf++)
#pragma unroll
        for (int nf = 0; nf < 8; nf++)
#pragma unroll
            for (int j = 0; j < 4; j++) C[mf][nf][j] = 0.0f;

    const int nch = Ktot >> 5;

#define PREFETCH(CH) do { \
    int _b = (CH) & 1; \
    uint32_t _aS = sbase + (uint32_t)(_b * STAGE * 4); \
    uint32_t _bhS = _aS + BH_OFF * 4; \
    uint32_t _blS = _aS + BL_OFF * 4; \
    int _kk = (CH) << 5; \
    const float* _sp = (_kk >= 128) ? oldp : accp; \
    int _sc = (_kk >= 128) ? (_kk - 128) : _kk; \
    _Pragma("unroll") \
    for (int _i = 0; _i < 4; _i++) { \
        int _idx = tid + _i * 256; \
        int _r = _idx >> 3, _c4 = _idx & 7; \
        int _gr = row0 + _r; \
        int _sz = (_gr < M) ? 16 : 0; \
        const float* _g = _sp + (size_t)min(_gr, M - 1) * 128 + _sc + _c4 * 4; \
        cp16(_aS + (uint32_t)((_r * 32 + _c4 * 4) * 4), _g, _sz); \
    } \
    _Pragma("unroll") \
    for (int _i = 0; _i < 2; _i++) { \
        int _idx = tid + _i * 256; \
        int _n = _idx >> 2, _c4 = _idx & 3; \
        cp16(_bhS + (uint32_t)((_n * HSTR + _c4 * 4) * 4), \
             Bhg + (size_t)_n * Kh + (_kk >> 1) + _c4 * 4, 16); \
        cp16(_blS + (uint32_t)((_n * HSTR + _c4 * 4) * 4), \
             Blg + (size_t)_n * Kh + (_kk >> 1) + _c4 * 4, 16); \
    } \
} while (0)

    PREFETCH(0);
    asm volatile("cp.async.commit_group;" ::: "memory");

    for (int ch = 0; ch < nch; ch++) {
        if (ch + 1 < nch) {
            PREFETCH(ch + 1);
            asm volatile("cp.async.commit_group;" ::: "memory");
            asm volatile("cp.async.wait_group 1;" ::: "memory");
        } else {
            asm volatile("cp.async.wait_group 0;" ::: "memory");
        }
        __syncthreads();

        int b = ch & 1;
        const float* As = sm + b * STAGE;
        unsigned* AHs = (unsigned*)(sm + b * STAGE + AH_OFF);
        const unsigned* BhS = (const unsigned*)(sm + b * STAGE + BH_OFF);
        const unsigned* BlS = (const unsigned*)(sm + b * STAGE + BL_OFF);

#pragma unroll
        for (int i = 0; i < 8; i++) {
            int idx = tid + i * 256;
            int r = idx >> 4, p = idx & 15;
            float2 x = *(const float2*)(As + r * 32 + 2 * p);
            AHs[r * HSTR + p] = cvt2h(x);
        }
        __syncthreads();

#pragma unroll
        for (int ks = 0; ks < 2; ks++) {
            int kb = ks * 8 + qc;
            uint32_t ah[2][4];
#pragma unroll
            for (int mf = 0; mf < 2; mf++) {
                int r0 = wr * 32 + mf * 16 + qr;
                ah[mf][0] = AHs[r0 * HSTR + kb];
                ah[mf][1] = AHs[(r0 + 8) * HSTR + kb];
                ah[mf][2] = AHs[r0 * HSTR + kb + 4];
                ah[mf][3] = AHs[(r0 + 8) * HSTR + kb + 4];
            }
            uint32_t bh[8][2], bl[8][2];
#pragma unroll
            for (int nf = 0; nf < 8; nf++) {
                int n = wc * 64 + nf * 8 + qr;
                bh[nf][0] = BhS[n * HSTR + kb];
                bh[nf][1] = BhS[n * HSTR + kb + 4];
                bl[nf][0] = BlS[n * HSTR + kb];
                bl[nf][1] = BlS[n * HSTR + kb + 4];
            }
#pragma unroll
            for (int mf = 0; mf < 2; mf++)
#pragma unroll
                for (int nf = 0; nf < 8; nf++) {
                    MMA_FP16(C[mf][nf], ah[mf], bh[nf]);
                    MMA_FP16(C[mf][nf], ah[mf], bl[nf]);
                }
        }
        __syncthreads();
    }

#pragma unroll
    for (int mf = 0; mf < 2; mf++) {
        int rA = row0 + wr * 32 + mf * 16 + qr;
#pragma unroll
        for (int nf = 0; nf < 8; nf++) {
            int c = wc * 64 + nf * 8 + qc * 2;
            if (rA < M) {
                float2 v;
                v.x = fmaxf(C[mf][nf][0], 0.f);
                v.y = fmaxf(C[mf][nf][1], 0.f);
                *(float2*)(out + (size_t)rA * 128 + c) = v;
            }
            if (rA + 8 < M) {
                float2 v;
                v.x = fmaxf(C[mf][nf][2], 0.f);
                v.y = fmaxf(C[mf][nf][3], 0.f);
                *(float2*)(out + (size_t)(rA + 8) * 128 + c) = v;
            }
        }
    }
}

// ---------------- final gather ----------------
__global__ void gather_out(const float* __restrict__ hSel,
                           const float* __restrict__ eB,
                           const int* __restrict__ map,
                           const int* __restrict__ pos,
                           const int* __restrict__ neg,
                           float* __restrict__ out) {
    int gw = (blockIdx.x * blockDim.x + threadIdx.x) >> 5;
    int lane = threadIdx.x & 31;
    const int TOT = BB + BB + NNEG;
    if (gw >= TOT) return;
    const float* src;
    if (gw < BB)          src = hSel + (size_t)gw * DD;
    else if (gw < 2 * BB) src = eB + (size_t)__ldg(map + pos[gw - BB]) * DD;
    else                  src = eB + (size_t)__ldg(map + neg[gw - 2 * BB]) * DD;
    ((float4*)out)[(size_t)gw * 32 + lane] = ((const float4*)src)[lane];
}

// ---------------- launch ----------------
extern "C" void kernel_launch(void* const* d_in, const int* in_sizes, int n_in,
                              void* d_out, int out_size) {
    const int* node_idx  = (const int*)d_in[0];
    const int* hedge_idx = (const int*)d_in[1];
    const int* edge_attr = (const int*)d_in[2];
    const int* v_dis     = (const int*)d_in[3];
    const int* src_h     = (const int*)d_in[4];
    const int* pos_ids   = (const int*)d_in[5];
    const int* neg_ids   = (const int*)d_in[6];
    const float* dis_emb = (const float*)d_in[7];
    const float* rel_emb = (const float*)d_in[8];
    const float* Wv_src  = (const float*)d_in[9];
    const float* Wv_self = (const float*)d_in[10];
    const float* We_src  = (const float*)d_in[11];
    const float* We_self = (const float*)d_in[12];
    float* out = (float*)d_out;

    float *hA, *hB, *eA, *eB, *acc, *relsum;
    int *cnt, *off, *csrh, *csraux, *csrn, *bsum, *flag, *map, *list, *cntr;
    unsigned *Bh, *Bl;
    cudaGetSymbolAddress((void**)&hA,     g_hA);
    cudaGetSymbolAddress((void**)&hB,     g_hB);
    cudaGetSymbolAddress((void**)&eA,     g_eA);
    cudaGetSymbolAddress((void**)&eB,     g_eB);
    cudaGetSymbolAddress((void**)&acc,    g_acc);
    cudaGetSymbolAddress((void**)&relsum, g_relsum);
    cudaGetSymbolAddress((void**)&cnt,    g_cnt);
    cudaGetSymbolAddress((void**)&off,    g_off);
    cudaGetSymbolAddress((void**)&csrh,   g_csr_h);
    cudaGetSymbolAddress((void**)&csraux, g_csr_aux);
    cudaGetSymbolAddress((void**)&csrn,   g_csr_n);
    cudaGetSymbolAddress((void**)&bsum,   g_bsum);
    cudaGetSymbolAddress((void**)&flag,   g_flag);
    cudaGetSymbolAddress((void**)&map,    g_map);
    cudaGetSymbolAddress((void**)&list,   g_list);
    cudaGetSymbolAddress((void**)&cntr,   g_cntr);
    cudaGetSymbolAddress((void**)&Bh,     g_Bh);
    cudaGetSymbolAddress((void**)&Bl,     g_Bl);

    static cudaStream_t s1 = nullptr;
    static cudaEvent_t evFork, evW, evFill, evM;
    if (!s1) {
        cudaStreamCreateWithFlags(&s1, cudaStreamNonBlocking);
        cudaEventCreateWithFlags(&evFork, cudaEventDisableTiming);
        cudaEventCreateWithFlags(&evW,    cudaEventDisableTiming);
        cudaEventCreateWithFlags(&evFill, cudaEventDisableTiming);
        cudaEventCreateWithFlags(&evM,    cudaEventDisableTiming);
    }

    const int SMEM_TC = STAGE * 2 * 4;
    cudaFuncSetAttribute(transform_mma, cudaFuncAttributeMaxDynamicSharedMemorySize, SMEM_TC);

    const int HW  = (NHH * 32 + 255) / 256;
    const int NW  = (NN * 32 + 255) / 256;
    const int NHB = (NHH + 127) / 128;
    const int NB  = (NN + 127) / 128;
    const int SELW = (BB * 32 + 255) / 256;
    const int SELB = (BB + 127) / 128;
    const int CMPW = (CAPC * 32 + 255) / 256;
    const int CMPB = (CAPC + 127) / 128;
    const int MARKB = (BB + NNEG + BB + 255) / 256;
    const int OW  = ((BB + BB + NNEG) * 32 + 255) / 256;
    const int o0 = 0, o1 = 8192, o2 = 16384, o3 = 32768, o4 = 49152;

    // ---- fork: prep work on s1 overlaps CSR build on s0 ----
    cudaEventRecord(evFork, 0);
    cudaStreamWaitEvent(s1, evFork, 0);
    wprep_all<<<256, 256, 0, s1>>>(Wv_src, Wv_self, We_src, We_self, Bh, Bl, flag, cntr);
    cudaEventRecord(evW, s1);

    // s0: CSR build
    cudaMemsetAsync(cnt, 0, (NHH + NN) * sizeof(int));
    count_kernel<<<(EN + 255) / 256, 256>>>(node_idx, hedge_idx, cnt);
    {
        const int NTOT = NHH + NN;
        int nb = (NTOT + 1023) / 1024;
        scan_pass1<<<nb, 256>>>(cnt, off, bsum, NTOT);
        scan_pass2<<<1, 32>>>(bsum, nb, off, NTOT);
        scan_pass3<<<(NTOT + 255) / 256, 256>>>(off, bsum, NTOT);
    }
    fill_kernel<<<(EN + 255) / 256, 256>>>(node_idx, hedge_idx, edge_attr, v_dis,
                                           off, off + NHH, cnt, csrh, csraux, csrn);
    cudaEventRecord(evFill, 0);

    // s1: mark after fill (flag/cntr already zeroed by wprep on s1)
    cudaStreamWaitEvent(s1, evFill, 0);
    mark_kernel<<<MARKB, 256, 0, s1>>>(pos_ids, neg_ids, src_h, off, csrh,
                                       flag, map, list, cntr);
    cudaEventRecord(evM, s1);

    // ---- k = 0 (s0 must see weights) ----
    v2e_gather_k0<<<HW, 256>>>(csraux, off, dis_emb, rel_emb, relsum, acc);
    cudaStreamWaitEvent(0, evW, 0);
    transform_mma<<<NHB, 256, SMEM_TC>>>(acc, nullptr, Bh + o0, Bl + o0, hA, NHH, nullptr, 128);

    e2v_gather<<<NW, 256>>>(csrn, off + NHH, hA, acc);
    transform_mma<<<NB, 256, SMEM_TC>>>(acc, nullptr, Bh + o1, Bl + o1, eA, NN, nullptr, 128);

    // ---- k = 1 ----
    v2e_gather<<<HW, 256>>>(csrh, off, eA, relsum, acc);
    transform_mma<<<NHB, 256, SMEM_TC>>>(acc, hA, Bh + o2, Bl + o2, hB, NHH, nullptr, 256);

    // k=1 ent: only marked nodes (compact); needs mark done.
    cudaStreamWaitEvent(0, evM, 0);
    e2v_gather_compact<<<CMPW, 256>>>(csrn, off + NHH, hB, list, cntr, eA, acc, hA);
    transform_mma<<<CMPB, 256, SMEM_TC>>>(acc, hA, Bh + o3, Bl + o3, eB, CAPC, cntr, 256);

    // ---- k = 2 (only the 512 source hedges) ----
    v2e_gather_sel<<<SELW, 256>>>(csrh, off, src_h, eB, map, relsum, hB, acc, eA);
    transform_mma<<<SELB, 256, SMEM_TC>>>(acc, eA, Bh + o4, Bl + o4, hA, BB, nullptr, 256);

    // ---- outputs ----
    gather_out<<<OW, 256>>>(hA, eB, map, pos_ids, neg_ids, out);
}

// round 16
// speedup vs baseline: 1.1045x; 1.0079x over previous
#include <cuda_runtime.h>
#include <cuda_bf16.h>
#include <cuda_fp16.h>
#include <cstdint>

// Problem constants (fixed dataset)
#define EN    500000
#define NN    100000
#define NHH   50000
#define DD    128
#define BB    512
#define NNEG  8192
#define CAPC  24576

// ---------------- device scratch ----------------
__device__ float g_hA[(size_t)NHH * DD];   // k0 hedge out; reused: compact old
__device__ float g_hB[(size_t)NHH * DD];
__device__ float g_eA[(size_t)NN * DD];    // k0 ent out; reused: old_sel for k2
__device__ float g_eB[(size_t)NN * DD];    // compact k1 ent out
__device__ float g_acc[(size_t)NN * DD];
__device__ float g_relsum[(size_t)NHH * DD];
__device__ int   g_cnt[NHH + NN];
__device__ int   g_off[NHH + NN + 1];
__device__ int   g_csr_h[EN];
__device__ int   g_csr_aux[EN];
__device__ int   g_csr_n[EN];
__device__ int   g_bsum[256];
__device__ int   g_flag[NN];
__device__ int   g_map[NN];
__device__ int   g_list[CAPC];
__device__ int   g_cntr[1];
__device__ unsigned g_Bh[65536];
__device__ unsigned g_Bl[65536];

// ---------------- helpers ----------------
__device__ __forceinline__ uint32_t smem_u32(const void* p) {
    uint32_t a;
    asm("{ .reg .u64 t; cvta.to.shared.u64 t, %1; cvt.u32.u64 %0, t; }" : "=r"(a) : "l"(p));
    return a;
}
__device__ __forceinline__ void split2h(float2 x, uint32_t& h, uint32_t& l) {
    __half2 hp = __floats2half2_rn(x.x, x.y);
    float2 hf = __half22float2(hp);
    __half2 lp = __floats2half2_rn(x.x - hf.x, x.y - hf.y);
    h = *reinterpret_cast<uint32_t*>(&hp);
    l = *reinterpret_cast<uint32_t*>(&lp);
}
__device__ __forceinline__ uint32_t cvt2h(float2 x) {
    __half2 hp = __floats2half2_rn(x.x, x.y);
    return *reinterpret_cast<uint32_t*>(&hp);
}
__device__ __forceinline__ void cp16(uint32_t s, const void* g, int sz) {
    asm volatile("cp.async.cg.shared.global [%0], [%1], 16, %2;"
                 :: "r"(s), "l"(g), "r"(sz) : "memory");
}
__device__ __forceinline__ void f4acc(float4& a, float4 b) {
    a.x += b.x; a.y += b.y; a.z += b.z; a.w += b.w;
}
#define MMA_FP16(c, a, b) \
    asm volatile("mma.sync.aligned.m16n8k16.row.col.f32.f16.f16.f32 " \
        "{%0,%1,%2,%3}, {%4,%5,%6,%7}, {%8,%9}, {%0,%1,%2,%3};" \
        : "+f"((c)[0]), "+f"((c)[1]), "+f"((c)[2]), "+f"((c)[3]) \
        : "r"((a)[0]), "r"((a)[1]), "r"((a)[2]), "r"((a)[3]), \
          "r"((b)[0]), "r"((b)[1]))

// ---------------- CSR build ----------------
__global__ void count_kernel(const int* __restrict__ node_idx,
                             const int* __restrict__ hedge_idx,
                             int* __restrict__ cnt) {
    int i = blockIdx.x * blockDim.x + threadIdx.x;
    if (i < EN) {
        atomicAdd(&cnt[hedge_idx[i]], 1);
        atomicAdd(&cnt[NHH + node_idx[i]], 1);
    }
}
// per-1024 block scan; bsum[b] = block total
__global__ void scan_pass1(const int* __restrict__ cnt, int* __restrict__ off,
                           int* __restrict__ bsum, int n) {
    __shared__ int wsum[8];
    int t = threadIdx.x, lane = t & 31, w = t >> 5;
    int b0 = blockIdx.x * 1024;
    int v[4], s = 0;
#pragma unroll
    for (int i = 0; i < 4; i++) {
        int idx = b0 + t * 4 + i;
        v[i] = (idx < n) ? cnt[idx] : 0;
        s += v[i];
    }
    int ps = s;
#pragma unroll
    for (int d = 1; d < 32; d <<= 1) {
        int x = __shfl_up_sync(0xffffffffu, ps, d);
        if (lane >= d) ps += x;
    }
    if (lane == 31) wsum[w] = ps;
    __syncthreads();
    if (t == 0) {
        int a = 0;
#pragma unroll
        for (int i = 0; i < 8; i++) { int x = wsum[i]; wsum[i] = a; a += x; }
        bsum[blockIdx.x] = a;
    }
    __syncthreads();
    int a = wsum[w] + ps - s;
#pragma unroll
    for (int i = 0; i < 4; i++) {
        int idx = b0 + t * 4 + i;
        if (idx < n) off[idx] = a;
        a += v[i];
    }
}
// adds prefix of block totals; each block computes its own prefix (bsum tiny, L2-hot)
__global__ void scan_pass3(int* __restrict__ off, const int* __restrict__ bsum, int n) {
    __shared__ int base;
    if (threadIdx.x < 32) {
        int myblk = blockIdx.x >> 2;   // 4 thread-blocks of 256 per 1024-elem scan block
        int a = 0;
        for (int b = threadIdx.x; b < myblk; b += 32) a += bsum[b];
#pragma unroll
        for (int d = 16; d; d >>= 1) a += __shfl_down_sync(0xffffffffu, a, d);
        if (threadIdx.x == 0) base = a;
    }
    __syncthreads();
    int i = blockIdx.x * blockDim.x + threadIdx.x;
    if (i < n) off[i] += base;
    if (i == 0) off[n] = 2 * EN;   // deterministic total
}
__global__ void fill_kernel(const int* __restrict__ node_idx,
                            const int* __restrict__ hedge_idx,
                            const int* __restrict__ edge_attr,
                            const int* __restrict__ v_dis,
                            const int* __restrict__ off_h, const int* __restrict__ off_n,
                            int* __restrict__ cnt,
                            int* __restrict__ csr_h, int* __restrict__ csr_aux,
                            int* __restrict__ csr_n) {
    int e = blockIdx.x * blockDim.x + threadIdx.x;
    if (e < EN) {
        int n = node_idx[e];
        int h = hedge_idx[e];
        int s = atomicSub(&cnt[h], 1) - 1;
        int p = off_h[h] + s;
        csr_h[p] = n;
        csr_aux[p] = (v_dis[n] << 16) | edge_attr[e];
        int t = atomicSub(&cnt[NHH + n], 1) - 1;
        csr_n[(off_n[n] - EN) + t] = h;
    }
}

// ---------------- mark needed nodes ----------------
__device__ __forceinline__ void mark_node(int n, int* flag, int* map, int* list, int* cntr) {
    if (atomicExch(&flag[n], 1) == 0) {
        int p = atomicAdd(cntr, 1);
        map[n] = p;
        list[p] = n;
    }
}
__global__ void mark_kernel(const int* __restrict__ pos, const int* __restrict__ neg,
                            const int* __restrict__ srcH,
                            const int* __restrict__ off, const int* __restrict__ csr_h,
                            int* __restrict__ flag, int* __restrict__ map,
                            int* __restrict__ list, int* __restrict__ cntr) {
    int t = blockIdx.x * blockDim.x + threadIdx.x;
    if (t < BB) {
        mark_node(__ldg(pos + t), flag, map, list, cntr);
    } else if (t < BB + NNEG) {
        mark_node(__ldg(neg + (t - BB)), flag, map, list, cntr);
    } else if (t < BB + NNEG + BB) {
        int h = __ldg(srcH + (t - BB - NNEG));
        int s = off[h], e = off[h + 1];
        for (int j = s; j < e; j++)
            mark_node(__ldg(csr_h + j), flag, map, list, cntr);
    }
}

// ---------------- gather aggregations (fp32, 2-way) ----------------
__global__ void v2e_gather_k0(const int* __restrict__ aux, const int* __restrict__ off,
                              const float* __restrict__ dis,
                              const float* __restrict__ rel,
                              float* __restrict__ relsum,
                              float* __restrict__ acc) {
    int h = (blockIdx.x * blockDim.x + threadIdx.x) >> 5;
    int lane = threadIdx.x & 31;
    if (h >= NHH) return;
    int s = off[h], e = off[h + 1];
    float4 ns = make_float4(0.f, 0.f, 0.f, 0.f);
    float4 rs = make_float4(0.f, 0.f, 0.f, 0.f);
    for (int j = s; j < e; j++) {
        int av = __ldg(aux + j);
        f4acc(ns, ((const float4*)(dis + (size_t)(av >> 16) * DD))[lane]);
        f4acc(rs, ((const float4*)(rel + (size_t)(av & 0xffff) * DD))[lane]);
    }
    ((float4*)(relsum + (size_t)h * DD))[lane] = rs;
    int c = 2 * (e - s);
    float inv = 1.0f / (float)(c > 1 ? c : 1);
    float4 o;
    o.x = (ns.x + rs.x) * inv; o.y = (ns.y + rs.y) * inv;
    o.z = (ns.z + rs.z) * inv; o.w = (ns.w + rs.w) * inv;
    ((float4*)(acc + (size_t)h * DD))[lane] = o;
}
__global__ void v2e_gather(const int* __restrict__ csr, const int* __restrict__ off,
                           const float* __restrict__ ent,
                           const float* __restrict__ relsum,
                           float* __restrict__ acc) {
    int h = (blockIdx.x * blockDim.x + threadIdx.x) >> 5;
    int lane = threadIdx.x & 31;
    if (h >= NHH) return;
    int s = off[h], e = off[h + 1];
    float4 s1 = ((const float4*)(relsum + (size_t)h * DD))[lane];
    float4 s2 = make_float4(0.f, 0.f, 0.f, 0.f);
    int j = s;
    for (; j + 1 < e; j += 2) {
        int i0 = __ldg(csr + j), i1 = __ldg(csr + j + 1);
        float4 a = ((const float4*)(ent + (size_t)i0 * DD))[lane];
        float4 b = ((const float4*)(ent + (size_t)i1 * DD))[lane];
        f4acc(s1, a); f4acc(s2, b);
    }
    if (j < e) {
        int i0 = __ldg(csr + j);
        f4acc(s1, ((const float4*)(ent + (size_t)i0 * DD))[lane]);
    }
    f4acc(s1, s2);
    int c = 2 * (e - s);
    float inv = 1.0f / (float)(c > 1 ? c : 1);
    s1.x *= inv; s1.y *= inv; s1.z *= inv; s1.w *= inv;
    ((float4*)(acc + (size_t)h * DD))[lane] = s1;
}
// k=2 selected hedges; ent = compact eB via map.
__global__ void v2e_gather_sel(const int* __restrict__ csr, const int* __restrict__ off,
                               const int* __restrict__ srcH,
                               const float* __restrict__ ent,
                               const int* __restrict__ map,
                               const float* __restrict__ relsum,
                               const float* __restrict__ oldfull,
                               float* __restrict__ acc_sel,
                               float* __restrict__ old_sel) {
    int b = (blockIdx.x * blockDim.x + threadIdx.x) >> 5;
    int lane = threadIdx.x & 31;
    if (b >= BB) return;
    int h = __ldg(srcH + b);
    int s = off[h], e = off[h + 1];
    float4 s1 = ((const float4*)(relsum + (size_t)h * DD))[lane];
    float4 s2 = make_float4(0.f, 0.f, 0.f, 0.f);
    int j = s;
    for (; j + 1 < e; j += 2) {
        int i0 = __ldg(map + __ldg(csr + j));
        int i1 = __ldg(map + __ldg(csr + j + 1));
        float4 a = ((const float4*)(ent + (size_t)i0 * DD))[lane];
        float4 c4 = ((const float4*)(ent + (size_t)i1 * DD))[lane];
        f4acc(s1, a); f4acc(s2, c4);
    }
    if (j < e) {
        int i0 = __ldg(map + __ldg(csr + j));
        f4acc(s1, ((const float4*)(ent + (size_t)i0 * DD))[lane]);
    }
    f4acc(s1, s2);
    int c = 2 * (e - s);
    float inv = 1.0f / (float)(c > 1 ? c : 1);
    s1.x *= inv; s1.y *= inv; s1.z *= inv; s1.w *= inv;
    ((float4*)(acc_sel + (size_t)b * DD))[lane] = s1;
    ((float4*)(old_sel + (size_t)b * DD))[lane] =
        ((const float4*)(oldfull + (size_t)h * DD))[lane];
}
__global__ void e2v_gather(const int* __restrict__ csr, const int* __restrict__ off,
                           const float* __restrict__ hemb,
                           float* __restrict__ acc) {
    int n = (blockIdx.x * blockDim.x + threadIdx.x) >> 5;
    int lane = threadIdx.x & 31;
    if (n >= NN) return;
    int s = off[n] - EN, e = off[n + 1] - EN;
    float4 s1 = make_float4(0.f, 0.f, 0.f, 0.f);
    float4 s2 = make_float4(0.f, 0.f, 0.f, 0.f);
    int j = s;
    for (; j + 1 < e; j += 2) {
        int i0 = __ldg(csr + j), i1 = __ldg(csr + j + 1);
        float4 a = ((const float4*)(hemb + (size_t)i0 * DD))[lane];
        float4 b = ((const float4*)(hemb + (size_t)i1 * DD))[lane];
        f4acc(s1, a); f4acc(s2, b);
    }
    if (j < e) {
        int i0 = __ldg(csr + j);
        f4acc(s1, ((const float4*)(hemb + (size_t)i0 * DD))[lane]);
    }
    f4acc(s1, s2);
    int c = e - s;
    float inv = 1.0f / (float)(c > 1 ? c : 1);
    s1.x *= inv; s1.y *= inv; s1.z *= inv; s1.w *= inv;
    ((float4*)(acc + (size_t)n * DD))[lane] = s1;
}
__global__ void e2v_gather_compact(const int* __restrict__ csr, const int* __restrict__ off,
                                   const float* __restrict__ hemb,
                                   const int* __restrict__ list, const int* __restrict__ cntr,
                                   const float* __restrict__ eA_full,
                                   float* __restrict__ acc,
                                   float* __restrict__ old_cmp) {
    int i = (blockIdx.x * blockDim.x + threadIdx.x) >> 5;
    int lane = threadIdx.x & 31;
    if (i >= __ldg(cntr)) return;
    int n = __ldg(list + i);
    int s = off[n] - EN, e = off[n + 1] - EN;
    float4 s1 = make_float4(0.f, 0.f, 0.f, 0.f);
    float4 s2 = make_float4(0.f, 0.f, 0.f, 0.f);
    int j = s;
    for (; j + 1 < e; j += 2) {
        int i0 = __ldg(csr + j), i1 = __ldg(csr + j + 1);
        float4 a = ((const float4*)(hemb + (size_t)i0 * DD))[lane];
        float4 b = ((const float4*)(hemb + (size_t)i1 * DD))[lane];
        f4acc(s1, a); f4acc(s2, b);
    }
    if (j < e) {
        int i0 = __ldg(csr + j);
        f4acc(s1, ((const float4*)(hemb + (size_t)i0 * DD))[lane]);
    }
    f4acc(s1, s2);
    int c = e - s;
    float inv = 1.0f / (float)(c > 1 ? c : 1);
    s1.x *= inv; s1.y *= inv; s1.z *= inv; s1.w *= inv;
    ((float4*)(acc + (size_t)i * DD))[lane] = s1;
    ((float4*)(old_cmp + (size_t)i * DD))[lane] =
        ((const float4*)(eA_full + (size_t)n * DD))[lane];
}

// ---------------- weight prep (+ zero flag/counter) ----------------
__global__ void wprep_all(const float* __restrict__ Wv_src, const float* __restrict__ Wv_self,
                          const float* __restrict__ We_src, const float* __restrict__ We_self,
                          unsigned* __restrict__ Bh, unsigned* __restrict__ Bl,
                          int* __restrict__ flag, int* __restrict__ cntr) {
    const size_t DS = (size_t)DD * DD;
    int idx = blockIdx.x * blockDim.x + threadIdx.x;
    for (int z = idx; z < NN; z += 65536) flag[z] = 0;
    if (idx == 0) cntr[0] = 0;
    if (idx >= 65536) return;
    int layer, base, Kh;
    if (idx < 8192)       { layer = 0; base = 0;     Kh = 64;  }
    else if (idx < 16384) { layer = 1; base = 8192;  Kh = 64;  }
    else if (idx < 32768) { layer = 2; base = 16384; Kh = 128; }
    else if (idx < 49152) { layer = 3; base = 32768; Kh = 128; }
    else                  { layer = 4; base = 49152; Kh = 128; }
    int li = idx - base;
    int n = li / Kh, kp = li % Kh;
    int k = kp * 2;
    const float *W1, *W2;
    switch (layer) {
        case 0: W1 = Wv_src;            W2 = nullptr;            break;
        case 1: W1 = We_src;            W2 = nullptr;            break;
        case 2: W1 = Wv_src + DS;       W2 = Wv_self + DS;       break;
        case 3: W1 = We_src + DS;       W2 = We_self + DS;       break;
        default:W1 = Wv_src + 2 * DS;   W2 = Wv_self + 2 * DS;   break;
    }
    const float* W = (k < 128) ? W1 : W2;
    int kk = k & 127;
    float2 x;
    x.x = W[(size_t)kk * 128 + n];
    x.y = W[(size_t)(kk + 1) * 128 + n];
    uint32_t h, l;
    split2h(x, h, l);
    Bh[idx] = h;
    Bl[idx] = l;
}

// ---------------- tensor-core transform (fp16 2-term) ----------------
#define AH_OFF  4096
#define BH_OFF  6656
#define BL_OFF  9216
#define STAGE   11776
#define HSTR    20
__global__ __launch_bounds__(256, 2) void transform_mma(
    const float* __restrict__ accp, const float* __restrict__ oldp,
    const unsigned* __restrict__ Bhg, const unsigned* __restrict__ Blg,
    float* __restrict__ out, int M, const int* __restrict__ Mdyn, int Ktot)
{
    if (Mdyn) M = __ldg(Mdyn);
    const int row0 = blockIdx.x * 128;
    if (row0 >= M) return;
    extern __shared__ float sm[];
    uint32_t sbase = smem_u32(sm);
    const int tid = threadIdx.x;
    const int wid = tid >> 5, lane = tid & 31;
    const int wr = wid & 3, wc = wid >> 2;
    const int qr = lane >> 2, qc = lane & 3;
    const int Kh = Ktot >> 1;

    float C[2][8][4];
#pragma unroll
    for (int mf = 0; mf < 2; mf++)
#pragma unroll
        for (int nf = 0; nf < 8; nf++)
#pragma unroll
            for (int j = 0; j < 4; j++) C[mf][nf][j] = 0.0f;

    const int nch = Ktot >> 5;

#define PREFETCH(CH) do { \
    int _b = (CH) & 1; \
    uint32_t _aS = sbase + (uint32_t)(_b * STAGE * 4); \
    uint32_t _bhS = _aS + BH_OFF * 4; \
    uint32_t _blS = _aS + BL_OFF * 4; \
    int _kk = (CH) << 5; \
    const float* _sp = (_kk >= 128) ? oldp : accp; \
    int _sc = (_kk >= 128) ? (_kk - 128) : _kk; \
    _Pragma("unroll") \
    for (int _i = 0; _i < 4; _i++) { \
        int _idx = tid + _i * 256; \
        int _r = _idx >> 3, _c4 = _idx & 7; \
        int _gr = row0 + _r; \
        int _sz = (_gr < M) ? 16 : 0; \
        const float* _g = _sp + (size_t)min(_gr, M - 1) * 128 + _sc + _c4 * 4; \
        cp16(_aS + (uint32_t)((_r * 32 + _c4 * 4) * 4), _g, _sz); \
    } \
    _Pragma("unroll") \
    for (int _i = 0; _i < 2; _i++) { \
        int _idx = tid + _i * 256; \
        int _n = _idx >> 2, _c4 = _idx & 3; \
        cp16(_bhS + (uint32_t)((_n * HSTR + _c4 * 4) * 4), \
             Bhg + (size_t)_n * Kh + (_kk >> 1) + _c4 * 4, 16); \
        cp16(_blS + (uint32_t)((_n * HSTR + _c4 * 4) * 4), \
             Blg + (size_t)_n * Kh + (_kk >> 1) + _c4 * 4, 16); \
    } \
} while (0)

    PREFETCH(0);
    asm volatile("cp.async.commit_group;" ::: "memory");

    for (int ch = 0; ch < nch; ch++) {
        if (ch + 1 < nch) {
            PREFETCH(ch + 1);
            asm volatile("cp.async.commit_group;" ::: "memory");
            asm volatile("cp.async.wait_group 1;" ::: "memory");
        } else {
            asm volatile("cp.async.wait_group 0;" ::: "memory");
        }
        __syncthreads();

        int b = ch & 1;
        const float* As = sm + b * STAGE;
        unsigned* AHs = (unsigned*)(sm + b * STAGE + AH_OFF);
        const unsigned* BhS = (const unsigned*)(sm + b * STAGE + BH_OFF);
        const unsigned* BlS = (const unsigned*)(sm + b * STAGE + BL_OFF);

#pragma unroll
        for (int i = 0; i < 8; i++) {
            int idx = tid + i * 256;
            int r = idx >> 4, p = idx & 15;
            float2 x = *(const float2*)(As + r * 32 + 2 * p);
            AHs[r * HSTR + p] = cvt2h(x);
        }
        __syncthreads();

#pragma unroll
        for (int ks = 0; ks < 2; ks++) {
            int kb = ks * 8 + qc;
            uint32_t ah[2][4];
#pragma unroll
            for (int mf = 0; mf < 2; mf++) {
                int r0 = wr * 32 + mf * 16 + qr;
                ah[mf][0] = AHs[r0 * HSTR + kb];
                ah[mf][1] = AHs[(r0 + 8) * HSTR + kb];
                ah[mf][2] = AHs[r0 * HSTR + kb + 4];
                ah[mf][3] = AHs[(r0 + 8) * HSTR + kb + 4];
            }
            uint32_t bh[8][2], bl[8][2];
#pragma unroll
            for (int nf = 0; nf < 8; nf++) {
                int n = wc * 64 + nf * 8 + qr;
                bh[nf][0] = BhS[n * HSTR + kb];
                bh[nf][1] = BhS[n * HSTR + kb + 4];
                bl[nf][0] = BlS[n * HSTR + kb];
                bl[nf][1] = BlS[n * HSTR + kb + 4];
            }
#pragma unroll
            for (int mf = 0; mf < 2; mf++)
#pragma unroll
                for (int nf = 0; nf < 8; nf++) {
                    MMA_FP16(C[mf][nf], ah[mf], bh[nf]);
                    MMA_FP16(C[mf][nf], ah[mf], bl[nf]);
                }
        }
        __syncthreads();
    }

#pragma unroll
    for (int mf = 0; mf < 2; mf++) {
        int rA = row0 + wr * 32 + mf * 16 + qr;
#pragma unroll
        for (int nf = 0; nf < 8; nf++) {
            int c = wc * 64 + nf * 8 + qc * 2;
            if (rA < M) {
                float2 v;
                v.x = fmaxf(C[mf][nf][0], 0.f);
                v.y = fmaxf(C[mf][nf][1], 0.f);
                *(float2*)(out + (size_t)rA * 128 + c) = v;
            }
            if (rA + 8 < M) {
                float2 v;
                v.x = fmaxf(C[mf][nf][2], 0.f);
                v.y = fmaxf(C[mf][nf][3], 0.f);
                *(float2*)(out + (size_t)(rA + 8) * 128 + c) = v;
            }
        }
    }
}

// ---------------- final gather (pos/neg only; h_out written directly by k2 transform) ----
__global__ void gather_out(const float* __restrict__ eB,
                           const int* __restrict__ map,
                           const int* __restrict__ pos,
                           const int* __restrict__ neg,
                           float* __restrict__ out) {
    int gw = (blockIdx.x * blockDim.x + threadIdx.x) >> 5;
    int lane = threadIdx.x & 31;
    const int TOT = BB + NNEG;
    if (gw >= TOT) return;
    int node = (gw < BB) ? __ldg(pos + gw) : __ldg(neg + (gw - BB));
    const float* src = eB + (size_t)__ldg(map + node) * DD;
    ((float4*)out)[(size_t)(BB + gw) * 32 + lane] = ((const float4*)src)[lane];
}

// ---------------- launch ----------------
extern "C" void kernel_launch(void* const* d_in, const int* in_sizes, int n_in,
                              void* d_out, int out_size) {
    const int* node_idx  = (const int*)d_in[0];
    const int* hedge_idx = (const int*)d_in[1];
    const int* edge_attr = (const int*)d_in[2];
    const int* v_dis     = (const int*)d_in[3];
    const int* src_h     = (const int*)d_in[4];
    const int* pos_ids   = (const int*)d_in[5];
    const int* neg_ids   = (const int*)d_in[6];
    const float* dis_emb = (const float*)d_in[7];
    const float* rel_emb = (const float*)d_in[8];
    const float* Wv_src  = (const float*)d_in[9];
    const float* Wv_self = (const float*)d_in[10];
    const float* We_src  = (const float*)d_in[11];
    const float* We_self = (const float*)d_in[12];
    float* out = (float*)d_out;

    float *hA, *hB, *eA, *eB, *acc, *relsum;
    int *cnt, *off, *csrh, *csraux, *csrn, *bsum, *flag, *map, *list, *cntr;
    unsigned *Bh, *Bl;
    cudaGetSymbolAddress((void**)&hA,     g_hA);
    cudaGetSymbolAddress((void**)&hB,     g_hB);
    cudaGetSymbolAddress((void**)&eA,     g_eA);
    cudaGetSymbolAddress((void**)&eB,     g_eB);
    cudaGetSymbolAddress((void**)&acc,    g_acc);
    cudaGetSymbolAddress((void**)&relsum, g_relsum);
    cudaGetSymbolAddress((void**)&cnt,    g_cnt);
    cudaGetSymbolAddress((void**)&off,    g_off);
    cudaGetSymbolAddress((void**)&csrh,   g_csr_h);
    cudaGetSymbolAddress((void**)&csraux, g_csr_aux);
    cudaGetSymbolAddress((void**)&csrn,   g_csr_n);
    cudaGetSymbolAddress((void**)&bsum,   g_bsum);
    cudaGetSymbolAddress((void**)&flag,   g_flag);
    cudaGetSymbolAddress((void**)&map,    g_map);
    cudaGetSymbolAddress((void**)&list,   g_list);
    cudaGetSymbolAddress((void**)&cntr,   g_cntr);
    cudaGetSymbolAddress((void**)&Bh,     g_Bh);
    cudaGetSymbolAddress((void**)&Bl,     g_Bl);

    static cudaStream_t s1 = nullptr;
    static cudaEvent_t evFork, evW, evFill, evM;
    if (!s1) {
        cudaStreamCreateWithFlags(&s1, cudaStreamNonBlocking);
        cudaEventCreateWithFlags(&evFork, cudaEventDisableTiming);
        cudaEventCreateWithFlags(&evW,    cudaEventDisableTiming);
        cudaEventCreateWithFlags(&evFill, cudaEventDisableTiming);
        cudaEventCreateWithFlags(&evM,    cudaEventDisableTiming);
    }

    const int SMEM_TC = STAGE * 2 * 4;
    cudaFuncSetAttribute(transform_mma, cudaFuncAttributeMaxDynamicSharedMemorySize, SMEM_TC);

    const int HW  = (NHH * 32 + 255) / 256;
    const int NW  = (NN * 32 + 255) / 256;
    const int NHB = (NHH + 127) / 128;
    const int NB  = (NN + 127) / 128;
    const int SELW = (BB * 32 + 255) / 256;
    const int SELB = (BB + 127) / 128;
    const int CMPW = (CAPC * 32 + 255) / 256;
    const int CMPB = (CAPC + 127) / 128;
    const int MARKB = (BB + NNEG + BB + 255) / 256;
    const int OW  = ((BB + NNEG) * 32 + 255) / 256;
    const int o0 = 0, o1 = 8192, o2 = 16384, o3 = 32768, o4 = 49152;

    // ---- fork: prep work on s1 overlaps CSR build on s0 ----
    cudaEventRecord(evFork, 0);
    cudaStreamWaitEvent(s1, evFork, 0);
    wprep_all<<<256, 256, 0, s1>>>(Wv_src, Wv_self, We_src, We_self, Bh, Bl, flag, cntr);
    cudaEventRecord(evW, s1);

    // s0: CSR build (scan_pass2 eliminated)
    cudaMemsetAsync(cnt, 0, (NHH + NN) * sizeof(int));
    count_kernel<<<(EN + 255) / 256, 256>>>(node_idx, hedge_idx, cnt);
    {
        const int NTOT = NHH + NN;
        int nb = (NTOT + 1023) / 1024;
        scan_pass1<<<nb, 256>>>(cnt, off, bsum, NTOT);
        scan_pass3<<<(NTOT + 255) / 256, 256>>>(off, bsum, NTOT);
    }
    fill_kernel<<<(EN + 255) / 256, 256>>>(node_idx, hedge_idx, edge_attr, v_dis,
                                           off, off + NHH, cnt, csrh, csraux, csrn);
    cudaEventRecord(evFill, 0);

    // s1: mark after fill (flag/cntr already zeroed by wprep on s1)
    cudaStreamWaitEvent(s1, evFill, 0);
    mark_kernel<<<MARKB, 256, 0, s1>>>(pos_ids, neg_ids, src_h, off, csrh,
                                       flag, map, list, cntr);
    cudaEventRecord(evM, s1);

    // ---- k = 0 (s0 must see weights) ----
    v2e_gather_k0<<<HW, 256>>>(csraux, off, dis_emb, rel_emb, relsum, acc);
    cudaStreamWaitEvent(0, evW, 0);
    transform_mma<<<NHB, 256, SMEM_TC>>>(acc, nullptr, Bh + o0, Bl + o0, hA, NHH, nullptr, 128);

    e2v_gather<<<NW, 256>>>(csrn, off + NHH, hA, acc);
    transform_mma<<<NB, 256, SMEM_TC>>>(acc, nullptr, Bh + o1, Bl + o1, eA, NN, nullptr, 128);

    // ---- k = 1 ----
    v2e_gather<<<HW, 256>>>(csrh, off, eA, relsum, acc);
    transform_mma<<<NHB, 256, SMEM_TC>>>(acc, hA, Bh + o2, Bl + o2, hB, NHH, nullptr, 256);

    // k=1 ent: only marked nodes (compact); needs mark done.
    cudaStreamWaitEvent(0, evM, 0);
    e2v_gather_compact<<<CMPW, 256>>>(csrn, off + NHH, hB, list, cntr, eA, acc, hA);
    transform_mma<<<CMPB, 256, SMEM_TC>>>(acc, hA, Bh + o3, Bl + o3, eB, CAPC, cntr, 256);

    // ---- k = 2 (512 source hedges; writes d_out rows [0,512) directly) ----
    v2e_gather_sel<<<SELW, 256>>>(csrh, off, src_h, eB, map, relsum, hB, acc, eA);
    transform_mma<<<SELB, 256, SMEM_TC>>>(acc, eA, Bh + o4, Bl + o4, out, BB, nullptr, 256);

    // ---- outputs: pos/neg rows only ----
    gather_out<<<OW, 256>>>(eB, map, pos_ids, neg_ids, out);
}

// round 17
// speedup vs baseline: 1.1132x; 1.0079x over previous
#include <cuda_runtime.h>
#include <cuda_bf16.h>
#include <cuda_fp16.h>
#include <cstdint>

// Problem constants (fixed dataset)
#define EN    500000
#define NN    100000
#define NHH   50000
#define DD    128
#define BB    512
#define NNEG  8192
#define CAPC  24576

// ---------------- device scratch ----------------
__device__ float g_hA[(size_t)NHH * DD];
__device__ float g_hB[(size_t)NHH * DD];
__device__ float g_eA[(size_t)NN * DD];
__device__ float g_eB[(size_t)NN * DD];
__device__ float g_acc[(size_t)NN * DD];
__device__ float g_relsum[(size_t)NHH * DD];
__device__ int   g_cnt[NHH + NN];
__device__ int   g_off[NHH + NN + 1];
__device__ int   g_csr_h[EN];
__device__ int   g_csr_aux[EN];
__device__ int   g_csr_n[EN];
__device__ int   g_bsum[256];
__device__ int   g_bflag[256];
__device__ int   g_flag[NN];
__device__ int   g_map[NN];
__device__ int   g_list[CAPC];
__device__ int   g_cntr[1];
__device__ unsigned g_Bh[65536];
__device__ unsigned g_Bl[65536];

// ---------------- helpers ----------------
__device__ __forceinline__ uint32_t smem_u32(const void* p) {
    uint32_t a;
    asm("{ .reg .u64 t; cvta.to.shared.u64 t, %1; cvt.u32.u64 %0, t; }" : "=r"(a) : "l"(p));
    return a;
}
__device__ __forceinline__ void split2h(float2 x, uint32_t& h, uint32_t& l) {
    __half2 hp = __floats2half2_rn(x.x, x.y);
    float2 hf = __half22float2(hp);
    __half2 lp = __floats2half2_rn(x.x - hf.x, x.y - hf.y);
    h = *reinterpret_cast<uint32_t*>(&hp);
    l = *reinterpret_cast<uint32_t*>(&lp);
}
__device__ __forceinline__ uint32_t cvt2h(float2 x) {
    __half2 hp = __floats2half2_rn(x.x, x.y);
    return *reinterpret_cast<uint32_t*>(&hp);
}
__device__ __forceinline__ void cp16(uint32_t s, const void* g, int sz) {
    asm volatile("cp.async.cg.shared.global [%0], [%1], 16, %2;"
                 :: "r"(s), "l"(g), "r"(sz) : "memory");
}
__device__ __forceinline__ void f4acc(float4& a, float4 b) {
    a.x += b.x; a.y += b.y; a.z += b.z; a.w += b.w;
}
#define MMA_FP16(c, a, b) \
    asm volatile("mma.sync.aligned.m16n8k16.row.col.f32.f16.f16.f32 " \
        "{%0,%1,%2,%3}, {%4,%5,%6,%7}, {%8,%9}, {%0,%1,%2,%3};" \
        : "+f"((c)[0]), "+f"((c)[1]), "+f"((c)[2]), "+f"((c)[3]) \
        : "r"((a)[0]), "r"((a)[1]), "r"((a)[2]), "r"((a)[3]), \
          "r"((b)[0]), "r"((b)[1]))

// ---------------- CSR build ----------------
// also re-zeroes scan flags (stream-ordered before scan_fused)
__global__ void count_kernel(const int* __restrict__ node_idx,
                             const int* __restrict__ hedge_idx,
                             int* __restrict__ cnt, int* __restrict__ bflag) {
    int i = blockIdx.x * blockDim.x + threadIdx.x;
    if (i < 256) bflag[i] = 0;
    if (i < EN) {
        atomicAdd(&cnt[hedge_idx[i]], 1);
        atomicAdd(&cnt[NHH + node_idx[i]], 1);
    }
}
// fused scan: per-1024 block local scan + decoupled lookback over block totals
__global__ void scan_fused(const int* __restrict__ cnt, int* __restrict__ off,
                           int* __restrict__ bsum, int* __restrict__ bflag, int n) {
    __shared__ int wsum[8];
    __shared__ int base;
    int t = threadIdx.x, lane = t & 31, w = t >> 5;
    int b0 = blockIdx.x * 1024;
    int v[4], s = 0;
#pragma unroll
    for (int i = 0; i < 4; i++) {
        int idx = b0 + t * 4 + i;
        v[i] = (idx < n) ? cnt[idx] : 0;
        s += v[i];
    }
    int ps = s;
#pragma unroll
    for (int d = 1; d < 32; d <<= 1) {
        int x = __shfl_up_sync(0xffffffffu, ps, d);
        if (lane >= d) ps += x;
    }
    if (lane == 31) wsum[w] = ps;
    __syncthreads();
    if (t == 0) {
        int a = 0;
#pragma unroll
        for (int i = 0; i < 8; i++) { int x = wsum[i]; wsum[i] = a; a += x; }
        bsum[blockIdx.x] = a;
        __threadfence();
        atomicExch(&bflag[blockIdx.x], 1);
    }
    __syncthreads();
    // lookback: warp 0 sums totals of earlier blocks
    if (t < 32) {
        int a = 0;
        for (int b = lane; b < blockIdx.x; b += 32) {
            while (atomicAdd(&bflag[b], 0) == 0) { }
            a += bsum[b];
        }
#pragma unroll
        for (int d = 16; d; d >>= 1) a += __shfl_down_sync(0xffffffffu, a, d);
        if (t == 0) base = a;
    }
    __syncthreads();
    int a = base + wsum[w] + ps - s;
#pragma unroll
    for (int i = 0; i < 4; i++) {
        int idx = b0 + t * 4 + i;
        if (idx < n) off[idx] = a;
        a += v[i];
    }
    if (b0 == 0 && t == 0) off[n] = 2 * EN;
}
__global__ void fill_kernel(const int* __restrict__ node_idx,
                            const int* __restrict__ hedge_idx,
                            const int* __restrict__ edge_attr,
                            const int* __restrict__ v_dis,
                            const int* __restrict__ off_h, const int* __restrict__ off_n,
                            int* __restrict__ cnt,
                            int* __restrict__ csr_h, int* __restrict__ csr_aux,
                            int* __restrict__ csr_n) {
    int e = blockIdx.x * blockDim.x + threadIdx.x;
    if (e < EN) {
        int n = node_idx[e];
        int h = hedge_idx[e];
        int s = atomicSub(&cnt[h], 1) - 1;
        int p = off_h[h] + s;
        csr_h[p] = n;
        csr_aux[p] = (v_dis[n] << 16) | edge_attr[e];
        int t = atomicSub(&cnt[NHH + n], 1) - 1;
        csr_n[(off_n[n] - EN) + t] = h;
    }
}

// ---------------- mark needed nodes ----------------
__device__ __forceinline__ void mark_node(int n, int* flag, int* map, int* list, int* cntr) {
    if (atomicExch(&flag[n], 1) == 0) {
        int p = atomicAdd(cntr, 1);
        map[n] = p;
        list[p] = n;
    }
}
__global__ void mark_kernel(const int* __restrict__ pos, const int* __restrict__ neg,
                            const int* __restrict__ srcH,
                            const int* __restrict__ off, const int* __restrict__ csr_h,
                            int* __restrict__ flag, int* __restrict__ map,
                            int* __restrict__ list, int* __restrict__ cntr) {
    int t = blockIdx.x * blockDim.x + threadIdx.x;
    if (t < BB) {
        mark_node(__ldg(pos + t), flag, map, list, cntr);
    } else if (t < BB + NNEG) {
        mark_node(__ldg(neg + (t - BB)), flag, map, list, cntr);
    } else if (t < BB + NNEG + BB) {
        int h = __ldg(srcH + (t - BB - NNEG));
        int s = off[h], e = off[h + 1];
        for (int j = s; j < e; j++)
            mark_node(__ldg(csr_h + j), flag, map, list, cntr);
    }
}

// ---------------- gather aggregations (fp32, 2-way) ----------------
__global__ void v2e_gather_k0(const int* __restrict__ aux, const int* __restrict__ off,
                              const float* __restrict__ dis,
                              const float* __restrict__ rel,
                              float* __restrict__ relsum,
                              float* __restrict__ acc) {
    int h = (blockIdx.x * blockDim.x + threadIdx.x) >> 5;
    int lane = threadIdx.x & 31;
    if (h >= NHH) return;
    int s = off[h], e = off[h + 1];
    float4 ns = make_float4(0.f, 0.f, 0.f, 0.f);
    float4 rs = make_float4(0.f, 0.f, 0.f, 0.f);
    for (int j = s; j < e; j++) {
        int av = __ldg(aux + j);
        f4acc(ns, ((const float4*)(dis + (size_t)(av >> 16) * DD))[lane]);
        f4acc(rs, ((const float4*)(rel + (size_t)(av & 0xffff) * DD))[lane]);
    }
    ((float4*)(relsum + (size_t)h * DD))[lane] = rs;
    int c = 2 * (e - s);
    float inv = 1.0f / (float)(c > 1 ? c : 1);
    float4 o;
    o.x = (ns.x + rs.x) * inv; o.y = (ns.y + rs.y) * inv;
    o.z = (ns.z + rs.z) * inv; o.w = (ns.w + rs.w) * inv;
    ((float4*)(acc + (size_t)h * DD))[lane] = o;
}
__global__ void v2e_gather(const int* __restrict__ csr, const int* __restrict__ off,
                           const float* __restrict__ ent,
                           const float* __restrict__ relsum,
                           float* __restrict__ acc) {
    int h = (blockIdx.x * blockDim.x + threadIdx.x) >> 5;
    int lane = threadIdx.x & 31;
    if (h >= NHH) return;
    int s = off[h], e = off[h + 1];
    float4 s1 = ((const float4*)(relsum + (size_t)h * DD))[lane];
    float4 s2 = make_float4(0.f, 0.f, 0.f, 0.f);
    int j = s;
    for (; j + 1 < e; j += 2) {
        int i0 = __ldg(csr + j), i1 = __ldg(csr + j + 1);
        float4 a = ((const float4*)(ent + (size_t)i0 * DD))[lane];
        float4 b = ((const float4*)(ent + (size_t)i1 * DD))[lane];
        f4acc(s1, a); f4acc(s2, b);
    }
    if (j < e) {
        int i0 = __ldg(csr + j);
        f4acc(s1, ((const float4*)(ent + (size_t)i0 * DD))[lane]);
    }
    f4acc(s1, s2);
    int c = 2 * (e - s);
    float inv = 1.0f / (float)(c > 1 ? c : 1);
    s1.x *= inv; s1.y *= inv; s1.z *= inv; s1.w *= inv;
    ((float4*)(acc + (size_t)h * DD))[lane] = s1;
}
__global__ void v2e_gather_sel(const int* __restrict__ csr, const int* __restrict__ off,
                               const int* __restrict__ srcH,
                               const float* __restrict__ ent,
                               const int* __restrict__ map,
                               const float* __restrict__ relsum,
                               const float* __restrict__ oldfull,
                               float* __restrict__ acc_sel,
                               float* __restrict__ old_sel) {
    int b = (blockIdx.x * blockDim.x + threadIdx.x) >> 5;
    int lane = threadIdx.x & 31;
    if (b >= BB) return;
    int h = __ldg(srcH + b);
    int s = off[h], e = off[h + 1];
    float4 s1 = ((const float4*)(relsum + (size_t)h * DD))[lane];
    float4 s2 = make_float4(0.f, 0.f, 0.f, 0.f);
    int j = s;
    for (; j + 1 < e; j += 2) {
        int i0 = __ldg(map + __ldg(csr + j));
        int i1 = __ldg(map + __ldg(csr + j + 1));
        float4 a = ((const float4*)(ent + (size_t)i0 * DD))[lane];
        float4 c4 = ((const float4*)(ent + (size_t)i1 * DD))[lane];
        f4acc(s1, a); f4acc(s2, c4);
    }
    if (j < e) {
        int i0 = __ldg(map + __ldg(csr + j));
        f4acc(s1, ((const float4*)(ent + (size_t)i0 * DD))[lane]);
    }
    f4acc(s1, s2);
    int c = 2 * (e - s);
    float inv = 1.0f / (float)(c > 1 ? c : 1);
    s1.x *= inv; s1.y *= inv; s1.z *= inv; s1.w *= inv;
    ((float4*)(acc_sel + (size_t)b * DD))[lane] = s1;
    ((float4*)(old_sel + (size_t)b * DD))[lane] =
        ((const float4*)(oldfull + (size_t)h * DD))[lane];
}
__global__ void e2v_gather(const int* __restrict__ csr, const int* __restrict__ off,
                           const float* __restrict__ hemb,
                           float* __restrict__ acc) {
    int n = (blockIdx.x * blockDim.x + threadIdx.x) >> 5;
    int lane = threadIdx.x & 31;
    if (n >= NN) return;
    int s = off[n] - EN, e = off[n + 1] - EN;
    float4 s1 = make_float4(0.f, 0.f, 0.f, 0.f);
    float4 s2 = make_float4(0.f, 0.f, 0.f, 0.f);
    int j = s;
    for (; j + 1 < e; j += 2) {
        int i0 = __ldg(csr + j), i1 = __ldg(csr + j + 1);
        float4 a = ((const float4*)(hemb + (size_t)i0 * DD))[lane];
        float4 b = ((const float4*)(hemb + (size_t)i1 * DD))[lane];
        f4acc(s1, a); f4acc(s2, b);
    }
    if (j < e) {
        int i0 = __ldg(csr + j);
        f4acc(s1, ((const float4*)(hemb + (size_t)i0 * DD))[lane]);
    }
    f4acc(s1, s2);
    int c = e - s;
    float inv = 1.0f / (float)(c > 1 ? c : 1);
    s1.x *= inv; s1.y *= inv; s1.z *= inv; s1.w *= inv;
    ((float4*)(acc + (size_t)n * DD))[lane] = s1;
}
__global__ void e2v_gather_compact(const int* __restrict__ csr, const int* __restrict__ off,
                                   const float* __restrict__ hemb,
                                   const int* __restrict__ list, const int* __restrict__ cntr,
                                   const float* __restrict__ eA_full,
                                   float* __restrict__ acc,
                                   float* __restrict__ old_cmp) {
    int i = (blockIdx.x * blockDim.x + threadIdx.x) >> 5;
    int lane = threadIdx.x & 31;
    if (i >= __ldg(cntr)) return;
    int n = __ldg(list + i);
    int s = off[n] - EN, e = off[n + 1] - EN;
    float4 s1 = make_float4(0.f, 0.f, 0.f, 0.f);
    float4 s2 = make_float4(0.f, 0.f, 0.f, 0.f);
    int j = s;
    for (; j + 1 < e; j += 2) {
        int i0 = __ldg(csr + j), i1 = __ldg(csr + j + 1);
        float4 a = ((const float4*)(hemb + (size_t)i0 * DD))[lane];
        float4 b = ((const float4*)(hemb + (size_t)i1 * DD))[lane];
        f4acc(s1, a); f4acc(s2, b);
    }
    if (j < e) {
        int i0 = __ldg(csr + j);
        f4acc(s1, ((const float4*)(hemb + (size_t)i0 * DD))[lane]);
    }
    f4acc(s1, s2);
    int c = e - s;
    float inv = 1.0f / (float)(c > 1 ? c : 1);
    s1.x *= inv; s1.y *= inv; s1.z *= inv; s1.w *= inv;
    ((float4*)(acc + (size_t)i * DD))[lane] = s1;
    ((float4*)(old_cmp + (size_t)i * DD))[lane] =
        ((const float4*)(eA_full + (size_t)n * DD))[lane];
}

// ---------------- weight prep (+ zero flag/counter) ----------------
__global__ void wprep_all(const float* __restrict__ Wv_src, const float* __restrict__ Wv_self,
                          const float* __restrict__ We_src, const float* __restrict__ We_self,
                          unsigned* __restrict__ Bh, unsigned* __restrict__ Bl,
                          int* __restrict__ flag, int* __restrict__ cntr) {
    const size_t DS = (size_t)DD * DD;
    int idx = blockIdx.x * blockDim.x + threadIdx.x;
    for (int z = idx; z < NN; z += 65536) flag[z] = 0;
    if (idx == 0) cntr[0] = 0;
    if (idx >= 65536) return;
    int layer, base, Kh;
    if (idx < 8192)       { layer = 0; base = 0;     Kh = 64;  }
    else if (idx < 16384) { layer = 1; base = 8192;  Kh = 64;  }
    else if (idx < 32768) { layer = 2; base = 16384; Kh = 128; }
    else if (idx < 49152) { layer = 3; base = 32768; Kh = 128; }
    else                  { layer = 4; base = 49152; Kh = 128; }
    int li = idx - base;
    int n = li / Kh, kp = li % Kh;
    int k = kp * 2;
    const float *W1, *W2;
    switch (layer) {
        case 0: W1 = Wv_src;            W2 = nullptr;            break;
        case 1: W1 = We_src;            W2 = nullptr;            break;
        case 2: W1 = Wv_src + DS;       W2 = Wv_self + DS;       break;
        case 3: W1 = We_src + DS;       W2 = We_self + DS;       break;
        default:W1 = Wv_src + 2 * DS;   W2 = Wv_self + 2 * DS;   break;
    }
    const float* W = (k < 128) ? W1 : W2;
    int kk = k & 127;
    float2 x;
    x.x = W[(size_t)kk * 128 + n];
    x.y = W[(size_t)(kk + 1) * 128 + n];
    uint32_t h, l;
    split2h(x, h, l);
    Bh[idx] = h;
    Bl[idx] = l;
}

// ---------------- tensor-core transform (fp16 2-term) ----------------
#define AH_OFF  4096
#define BH_OFF  6656
#define BL_OFF  9216
#define STAGE   11776
#define HSTR    20
__global__ __launch_bounds__(256, 2) void transform_mma(
    const float* __restrict__ accp, const float* __restrict__ oldp,
    const unsigned* __restrict__ Bhg, const unsigned* __restrict__ Blg,
    float* __restrict__ out, int M, const int* __restrict__ Mdyn, int Ktot)
{
    if (Mdyn) M = __ldg(Mdyn);
    const int row0 = blockIdx.x * 128;
    if (row0 >= M) return;
    extern __shared__ float sm[];
    uint32_t sbase = smem_u32(sm);
    const int tid = threadIdx.x;
    const int wid = tid >> 5, lane = tid & 31;
    const int wr = wid & 3, wc = wid >> 2;
    const int qr = lane >> 2, qc = lane & 3;
    const int Kh = Ktot >> 1;

    float C[2][8][4];
#pragma unroll
    for (int mf = 0; mf < 2; mf++)
#pragma unroll
        for (int nf = 0; nf < 8; nf++)
#pragma unroll
            for (int j = 0; j < 4; j++) C[mf][nf][j] = 0.0f;

    const int nch = Ktot >> 5;

#define PREFETCH(CH) do { \
    int _b = (CH) & 1; \
    uint32_t _aS = sbase + (uint32_t)(_b * STAGE * 4); \
    uint32_t _bhS = _aS + BH_OFF * 4; \
    uint32_t _blS = _aS + BL_OFF * 4; \
    int _kk = (CH) << 5; \
    const float* _sp = (_kk >= 128) ? oldp : accp; \
    int _sc = (_kk >= 128) ? (_kk - 128) : _kk; \
    _Pragma("unroll") \
    for (int _i = 0; _i < 4; _i++) { \
        int _idx = tid + _i * 256; \
        int _r = _idx >> 3, _c4 = _idx & 7; \
        int _gr = row0 + _r; \
        int _sz = (_gr < M) ? 16 : 0; \
        const float* _g = _sp + (size_t)min(_gr, M - 1) * 128 + _sc + _c4 * 4; \
        cp16(_aS + (uint32_t)((_r * 32 + _c4 * 4) * 4), _g, _sz); \
    } \
    _Pragma("unroll") \
    for (int _i = 0; _i < 2; _i++) { \
        int _idx = tid + _i * 256; \
        int _n = _idx >> 2, _c4 = _idx & 3; \
        cp16(_bhS + (uint32_t)((_n * HSTR + _c4 * 4) * 4), \
             Bhg + (size_t)_n * Kh + (_kk >> 1) + _c4 * 4, 16); \
        cp16(_blS + (uint32_t)((_n * HSTR + _c4 * 4) * 4), \
             Blg + (size_t)_n * Kh + (_kk >> 1) + _c4 * 4, 16); \
    } \
} while (0)

    PREFETCH(0);
    asm volatile("cp.async.commit_group;" ::: "memory");

    for (int ch = 0; ch < nch; ch++) {
        if (ch + 1 < nch) {
            PREFETCH(ch + 1);
            asm volatile("cp.async.commit_group;" ::: "memory");
            asm volatile("cp.async.wait_group 1;" ::: "memory");
        } else {
            asm volatile("cp.async.wait_group 0;" ::: "memory");
        }
        __syncthreads();

        int b = ch & 1;
        const float* As = sm + b * STAGE;
        unsigned* AHs = (unsigned*)(sm + b * STAGE + AH_OFF);
        const unsigned* BhS = (const unsigned*)(sm + b * STAGE + BH_OFF);
        const unsigned* BlS = (const unsigned*)(sm + b * STAGE + BL_OFF);

#pragma unroll
        for (int i = 0; i < 8; i++) {
            int idx = tid + i * 256;
            int r = idx >> 4, p = idx & 15;
            float2 x = *(const float2*)(As + r * 32 + 2 * p);
            AHs[r * HSTR + p] = cvt2h(x);
        }
        __syncthreads();

#pragma unroll
        for (int ks = 0; ks < 2; ks++) {
            int kb = ks * 8 + qc;
            uint32_t ah[2][4];
#pragma unroll
            for (int mf = 0; mf < 2; mf++) {
                int r0 = wr * 32 + mf * 16 + qr;
                ah[mf][0] = AHs[r0 * HSTR + kb];
                ah[mf][1] = AHs[(r0 + 8) * HSTR + kb];
                ah[mf][2] = AHs[r0 * HSTR + kb + 4];
                ah[mf][3] = AHs[(r0 + 8) * HSTR + kb + 4];
            }
            uint32_t bh[8][2], bl[8][2];
#pragma unroll
            for (int nf = 0; nf < 8; nf++) {
                int n = wc * 64 + nf * 8 + qr;
                bh[nf][0] = BhS[n * HSTR + kb];
                bh[nf][1] = BhS[n * HSTR + kb + 4];
                bl[nf][0] = BlS[n * HSTR + kb];
                bl[nf][1] = BlS[n * HSTR + kb + 4];
            }
#pragma unroll
            for (int mf = 0; mf < 2; mf++)
#pragma unroll
                for (int nf = 0; nf < 8; nf++) {
                    MMA_FP16(C[mf][nf], ah[mf], bh[nf]);
                    MMA_FP16(C[mf][nf], ah[mf], bl[nf]);
                }
        }
        __syncthreads();
    }

#pragma unroll
    for (int mf = 0; mf < 2; mf++) {
        int rA = row0 + wr * 32 + mf * 16 + qr;
#pragma unroll
        for (int nf = 0; nf < 8; nf++) {
            int c = wc * 64 + nf * 8 + qc * 2;
            if (rA < M) {
                float2 v;
                v.x = fmaxf(C[mf][nf][0], 0.f);
                v.y = fmaxf(C[mf][nf][1], 0.f);
                *(float2*)(out + (size_t)rA * 128 + c) = v;
            }
            if (rA + 8 < M) {
                float2 v;
                v.x = fmaxf(C[mf][nf][2], 0.f);
                v.y = fmaxf(C[mf][nf][3], 0.f);
                *(float2*)(out + (size_t)(rA + 8) * 128 + c) = v;
            }
        }
    }
}

// ---------------- final gather (pos/neg only) ----------------
__global__ void gather_out(const float* __restrict__ eB,
                           const int* __restrict__ map,
                           const int* __restrict__ pos,
                           const int* __restrict__ neg,
                           float* __restrict__ out) {
    int gw = (blockIdx.x * blockDim.x + threadIdx.x) >> 5;
    int lane = threadIdx.x & 31;
    const int TOT = BB + NNEG;
    if (gw >= TOT) return;
    int node = (gw < BB) ? __ldg(pos + gw) : __ldg(neg + (gw - BB));
    const float* src = eB + (size_t)__ldg(map + node) * DD;
    ((float4*)out)[(size_t)(BB + gw) * 32 + lane] = ((const float4*)src)[lane];
}

// ---------------- launch ----------------
extern "C" void kernel_launch(void* const* d_in, const int* in_sizes, int n_in,
                              void* d_out, int out_size) {
    const int* node_idx  = (const int*)d_in[0];
    const int* hedge_idx = (const int*)d_in[1];
    const int* edge_attr = (const int*)d_in[2];
    const int* v_dis     = (const int*)d_in[3];
    const int* src_h     = (const int*)d_in[4];
    const int* pos_ids   = (const int*)d_in[5];
    const int* neg_ids   = (const int*)d_in[6];
    const float* dis_emb = (const float*)d_in[7];
    const float* rel_emb = (const float*)d_in[8];
    const float* Wv_src  = (const float*)d_in[9];
    const float* Wv_self = (const float*)d_in[10];
    const float* We_src  = (const float*)d_in[11];
    const float* We_self = (const float*)d_in[12];
    float* out = (float*)d_out;

    float *hA, *hB, *eA, *eB, *acc, *relsum;
    int *cnt, *off, *csrh, *csraux, *csrn, *bsum, *bflag, *flag, *map, *list, *cntr;
    unsigned *Bh, *Bl;
    cudaGetSymbolAddress((void**)&hA,     g_hA);
    cudaGetSymbolAddress((void**)&hB,     g_hB);
    cudaGetSymbolAddress((void**)&eA,     g_eA);
    cudaGetSymbolAddress((void**)&eB,     g_eB);
    cudaGetSymbolAddress((void**)&acc,    g_acc);
    cudaGetSymbolAddress((void**)&relsum, g_relsum);
    cudaGetSymbolAddress((void**)&cnt,    g_cnt);
    cudaGetSymbolAddress((void**)&off,    g_off);
    cudaGetSymbolAddress((void**)&csrh,   g_csr_h);
    cudaGetSymbolAddress((void**)&csraux, g_csr_aux);
    cudaGetSymbolAddress((void**)&csrn,   g_csr_n);
    cudaGetSymbolAddress((void**)&bsum,   g_bsum);
    cudaGetSymbolAddress((void**)&bflag,  g_bflag);
    cudaGetSymbolAddress((void**)&flag,   g_flag);
    cudaGetSymbolAddress((void**)&map,    g_map);
    cudaGetSymbolAddress((void**)&list,   g_list);
    cudaGetSymbolAddress((void**)&cntr,   g_cntr);
    cudaGetSymbolAddress((void**)&Bh,     g_Bh);
    cudaGetSymbolAddress((void**)&Bl,     g_Bl);

    static cudaStream_t s1 = nullptr;
    static cudaEvent_t evFork, evW, evFill, evM, evEB, evOut;
    if (!s1) {
        cudaStreamCreateWithFlags(&s1, cudaStreamNonBlocking);
        cudaEventCreateWithFlags(&evFork, cudaEventDisableTiming);
        cudaEventCreateWithFlags(&evW,    cudaEventDisableTiming);
        cudaEventCreateWithFlags(&evFill, cudaEventDisableTiming);
        cudaEventCreateWithFlags(&evM,    cudaEventDisableTiming);
        cudaEventCreateWithFlags(&evEB,   cudaEventDisableTiming);
        cudaEventCreateWithFlags(&evOut,  cudaEventDisableTiming);
    }

    const int SMEM_TC = STAGE * 2 * 4;
    cudaFuncSetAttribute(transform_mma, cudaFuncAttributeMaxDynamicSharedMemorySize, SMEM_TC);

    const int HW  = (NHH * 32 + 255) / 256;
    const int NW  = (NN * 32 + 255) / 256;
    const int NHB = (NHH + 127) / 128;
    const int NB  = (NN + 127) / 128;
    const int SELW = (BB * 32 + 255) / 256;
    const int SELB = (BB + 127) / 128;
    const int CMPW = (CAPC * 32 + 255) / 256;
    const int CMPB = (CAPC + 127) / 128;
    const int MARKB = (BB + NNEG + BB + 255) / 256;
    const int OW  = ((BB + NNEG) * 32 + 255) / 256;
    const int o0 = 0, o1 = 8192, o2 = 16384, o3 = 32768, o4 = 49152;

    // ---- fork: prep work on s1 overlaps CSR build on s0 ----
    cudaEventRecord(evFork, 0);
    cudaStreamWaitEvent(s1, evFork, 0);
    wprep_all<<<256, 256, 0, s1>>>(Wv_src, Wv_self, We_src, We_self, Bh, Bl, flag, cntr);
    cudaEventRecord(evW, s1);

    // s0: CSR build (fused scan)
    cudaMemsetAsync(cnt, 0, (NHH + NN) * sizeof(int));
    count_kernel<<<(EN + 255) / 256, 256>>>(node_idx, hedge_idx, cnt, bflag);
    {
        const int NTOT = NHH + NN;
        int nb = (NTOT + 1023) / 1024;
        scan_fused<<<nb, 256>>>(cnt, off, bsum, bflag, NTOT);
    }
    fill_kernel<<<(EN + 255) / 256, 256>>>(node_idx, hedge_idx, edge_attr, v_dis,
                                           off, off + NHH, cnt, csrh, csraux, csrn);
    cudaEventRecord(evFill, 0);

    // s1: mark after fill
    cudaStreamWaitEvent(s1, evFill, 0);
    mark_kernel<<<MARKB, 256, 0, s1>>>(pos_ids, neg_ids, src_h, off, csrh,
                                       flag, map, list, cntr);
    cudaEventRecord(evM, s1);

    // ---- k = 0 ----
    v2e_gather_k0<<<HW, 256>>>(csraux, off, dis_emb, rel_emb, relsum, acc);
    cudaStreamWaitEvent(0, evW, 0);
    transform_mma<<<NHB, 256, SMEM_TC>>>(acc, nullptr, Bh + o0, Bl + o0, hA, NHH, nullptr, 128);

    e2v_gather<<<NW, 256>>>(csrn, off + NHH, hA, acc);
    transform_mma<<<NB, 256, SMEM_TC>>>(acc, nullptr, Bh + o1, Bl + o1, eA, NN, nullptr, 128);

    // ---- k = 1 ----
    v2e_gather<<<HW, 256>>>(csrh, off, eA, relsum, acc);
    transform_mma<<<NHB, 256, SMEM_TC>>>(acc, hA, Bh + o2, Bl + o2, hB, NHH, nullptr, 256);

    // k=1 ent: compact
    cudaStreamWaitEvent(0, evM, 0);
    e2v_gather_compact<<<CMPW, 256>>>(csrn, off + NHH, hB, list, cntr, eA, acc, hA);
    transform_mma<<<CMPB, 256, SMEM_TC>>>(acc, hA, Bh + o3, Bl + o3, eB, CAPC, cntr, 256);
    cudaEventRecord(evEB, 0);

    // s1: pos/neg output rows overlap the k2 chain (disjoint d_out regions)
    cudaStreamWaitEvent(s1, evEB, 0);
    gather_out<<<OW, 256, 0, s1>>>(eB, map, pos_ids, neg_ids, out);
    cudaEventRecord(evOut, s1);

    // ---- k = 2 on s0 (writes d_out rows [0,512)) ----
    v2e_gather_sel<<<SELW, 256>>>(csrh, off, src_h, eB, map, relsum, hB, acc, eA);
    transform_mma<<<SELB, 256, SMEM_TC>>>(acc, eA, Bh + o4, Bl + o4, out, BB, nullptr, 256);

    // join
    cudaStreamWaitEvent(0, evOut, 0);
}